// round 8
// baseline (speedup 1.0000x reference)
#include <cuda_runtime.h>
#include <cuda_fp16.h>
#include <math.h>
#include <cstdint>

#define BB 32
#define TT 2048
#define HH 1024

// Scratch (allocation-free rule: __device__ globals)
__device__ float g_decfea[BB * HH];
__device__ float g_scores[BB * TT];
__device__ __half g_B[(size_t)HH * HH];            // W_prev fp16 (2 MB), plain
// A split planes: per 32-k slab of each row: [32 hi | 32 lo] fp16 = 128B
__device__ __half g_A[(size_t)BB * TT * HH * 2];   // prev_s (268 MB)

// ---------------------------------------------------------------------------
// PTX helpers
// ---------------------------------------------------------------------------
__device__ __forceinline__ uint32_t smem_u32(const void* p) {
    uint32_t a;
    asm("{ .reg .u64 t; cvta.to.shared.u64 t, %1; cvt.u32.u64 %0, t; }" : "=r"(a) : "l"(p));
    return a;
}
__device__ __forceinline__ void cp_async16(uint32_t dst, const void* src) {
    asm volatile("cp.async.cg.shared.global [%0], [%1], 16;" :: "r"(dst), "l"(src) : "memory");
}
__device__ __forceinline__ void cp_commit() {
    asm volatile("cp.async.commit_group;" ::: "memory");
}
template <int N>
__device__ __forceinline__ void cp_wait() {
    asm volatile("cp.async.wait_group %0;" :: "n"(N) : "memory");
}
__device__ __forceinline__ void ldsm_x4(uint32_t addr, uint32_t& r0, uint32_t& r1,
                                        uint32_t& r2, uint32_t& r3) {
    asm volatile("ldmatrix.sync.aligned.m8n8.x4.shared.b16 {%0,%1,%2,%3}, [%4];"
                 : "=r"(r0), "=r"(r1), "=r"(r2), "=r"(r3) : "r"(addr));
}
__device__ __forceinline__ void mma_f32(float* c, const uint32_t* a, const uint32_t* b) {
    asm volatile(
        "mma.sync.aligned.m16n8k16.row.col.f32.f16.f16.f32 "
        "{%0,%1,%2,%3}, {%4,%5,%6,%7}, {%8,%9}, {%0,%1,%2,%3};"
        : "+f"(c[0]), "+f"(c[1]), "+f"(c[2]), "+f"(c[3])
        : "r"(a[0]), "r"(a[1]), "r"(a[2]), "r"(a[3]), "r"(b[0]), "r"(b[1]));
}
__device__ __forceinline__ float fast_tanh(float x) {
    float y;
    asm("tanh.approx.f32 %0, %1;" : "=f"(y) : "f"(x));
    return y;
}
__device__ __forceinline__ uint32_t pack_h2(__half a, __half b) {
    __half2 t = __halves2half2(a, b);
    return *reinterpret_cast<uint32_t*>(&t);
}
// fp16 split, UNSCALED residual: hi = f16(x), lo = f16(x - hi).
__device__ __forceinline__ void split2h(float x, float y, uint32_t& hi, uint32_t& lo) {
    __half hx = __float2half_rn(x), hy = __float2half_rn(y);
    __half lx = __float2half_rn(x - __half2float(hx));
    __half ly = __float2half_rn(y - __half2float(hy));
    hi = pack_h2(hx, hy);
    lo = pack_h2(lx, ly);
}

// ---------------------------------------------------------------------------
// A prepack: fp32 rows -> [32 hi | 32 lo] fp16 per 32-k slab.
// ---------------------------------------------------------------------------
__global__ void conv_split_kernel(const float* __restrict__ src,
                                  __half* __restrict__ dst) {
    size_t t = (size_t)blockIdx.x * 256 + threadIdx.x;
    int j = (int)(t & 3);
    size_t chunk = t >> 2;  // row*32 + slab
    const float* s = src + chunk * 32 + (size_t)j * 8;
    float4 f0 = *(const float4*)s;
    float4 f1 = *(const float4*)(s + 4);
    uint4 hi, lo;
    split2h(f0.x, f0.y, hi.x, lo.x);
    split2h(f0.z, f0.w, hi.y, lo.y);
    split2h(f1.x, f1.y, hi.z, lo.z);
    split2h(f1.z, f1.w, hi.w, lo.w);
    __half* d = dst + chunk * 64;
    *(uint4*)(d + j * 8) = hi;
    *(uint4*)(d + 32 + j * 8) = lo;
}

// B prepack: plain fp32 -> fp16 (row-major, k contiguous)
__global__ void conv_b_kernel(const float* __restrict__ src,
                              __half* __restrict__ dst) {
    size_t t = (size_t)blockIdx.x * 256 + threadIdx.x;  // x8 elems
    const float* s = src + t * 8;
    float4 f0 = *(const float4*)s;
    float4 f1 = *(const float4*)(s + 4);
    uint4 o;
    o.x = pack_h2(__float2half_rn(f0.x), __float2half_rn(f0.y));
    o.y = pack_h2(__float2half_rn(f0.z), __float2half_rn(f0.w));
    o.z = pack_h2(__float2half_rn(f1.x), __float2half_rn(f1.y));
    o.w = pack_h2(__float2half_rn(f1.z), __float2half_rn(f1.w));
    *(uint4*)(dst + t * 8) = o;
}

// ---------------------------------------------------------------------------
// Kernel 1: dec_fea[b,d] = sum_h s_t[b,h] * W_s[d,h] + b_s[d]   (fp32, small)
// ---------------------------------------------------------------------------
__global__ void dec_fea_kernel(const float* __restrict__ s_t,
                               const float* __restrict__ W_s,
                               const float* __restrict__ b_s) {
    __shared__ float Ss[32][BB + 1];
    __shared__ float Ws[32][128 + 1];
    const int d0 = blockIdx.x * 128;
    const int tid = threadIdx.x;
    const int dl = tid & 127;
    const int bq = tid >> 7;

    float acc[16];
#pragma unroll
    for (int i = 0; i < 16; i++) acc[i] = 0.f;

    for (int k0 = 0; k0 < HH; k0 += 32) {
        for (int i = tid; i < BB * 32; i += 256) {
            int bb = i >> 5, kk = i & 31;
            Ss[kk][bb] = s_t[bb * HH + k0 + kk];
        }
        for (int i = tid; i < 128 * 32; i += 256) {
            int dd = i >> 5, kk = i & 31;
            Ws[kk][dd] = W_s[(d0 + dd) * HH + k0 + kk];
        }
        __syncthreads();
#pragma unroll
        for (int kk = 0; kk < 32; kk++) {
            float w = Ws[kk][dl];
#pragma unroll
            for (int i = 0; i < 16; i++)
                acc[i] += w * Ss[kk][bq * 16 + i];
        }
        __syncthreads();
    }
    float bias = b_s[d0 + dl];
#pragma unroll
    for (int i = 0; i < 16; i++)
        g_decfea[(bq * 16 + i) * HH + d0 + dl] = acc[i] + bias;
}

// ---------------------------------------------------------------------------
// Kernel 2: fused score GEMM, fp16x2 split-A mma.sync (both passes f32-acc).
// CTA: 128 M x (8 n-chunks of 128), 4-stage cp.async ring, 1 barrier/slab.
// 16 warps = 4(m) x 4(n); warp tile 32m x 32n; SMEM rows padded to 80B.
// ---------------------------------------------------------------------------
constexpr int PLANE = 10240;        // 128 rows * 80B
constexpr int STAGE = 30720;        // A hi + A lo + B (one plane each)
constexpr int NSTAGE = 4;
constexpr int V_OFF = STAGE * NSTAGE;          // 122880
constexpr int DEC_OFF = V_OFF + 4096;
constexpr int RED_OFF = DEC_OFF + 4096;
constexpr int SMEM_BYTES = RED_OFF + 8192;     // 139264

__device__ __forceinline__ void fill_slab(uint32_t sb, int st, int s,
                                          int row0, int n0, int tid) {
#pragma unroll
    for (int it = 0; it < 3; it++) {
        int idx = tid + it * 512;           // 0..1535
        if (idx < 1024) {
            int m = idx >> 3;
            int p = (idx >> 2) & 1;
            int c = idx & 3;
            const __half* src =
                g_A + ((size_t)(row0 + m) * 32 + s) * 64 + p * 32 + c * 8;
            uint32_t dst = sb + (uint32_t)(st * STAGE) + p * PLANE + m * 80 + c * 16;
            cp_async16(dst, src);
        } else {
            int loc = idx - 1024;
            int m = loc >> 2;
            int c = loc & 3;
            const __half* src = g_B + (size_t)(n0 + m) * HH + s * 32 + c * 8;
            uint32_t dst = sb + (uint32_t)(st * STAGE) + 2 * PLANE + m * 80 + c * 16;
            cp_async16(dst, src);
        }
    }
}

__global__ void __launch_bounds__(512, 1)
score_kernel(const float* __restrict__ vvec) {
    extern __shared__ char smem[];
    const uint32_t sb = smem_u32(smem);
    const int tid = threadIdx.x;
    const int warp = tid >> 5;
    const int lane = tid & 31;
    const int wm = warp >> 2;   // 0..3
    const int wn = warp & 3;    // 0..3
    const int row0 = blockIdx.x * 128;
    const int b = blockIdx.x >> 4;

    float* v_s = (float*)(smem + V_OFF);
    float* dec_s = (float*)(smem + DEC_OFF);
    for (int i = tid; i < 1024; i += 512) {
        v_s[i] = vvec[i];
        dec_s[i] = g_decfea[b * 1024 + i];
    }
    __syncthreads();

    const int a_row = wm * 32 + (lane & 15);                    // + mt*16
    const int a_col = ((lane >> 4) << 4);                       // 0 or 16 bytes
    const int b_row = wn * 32 + (((lane >> 4) & 1) << 3) + (lane & 7);  // + q*16
    const int b_col = (((lane >> 3) & 1) << 4);

    float msum[4];
#pragma unroll
    for (int i = 0; i < 4; i++) msum[i] = 0.f;

#pragma unroll 1
    for (int nc = 0; nc < 8; nc++) {
        const int n0 = nc * 128;
        float acc[2][4][4];
#pragma unroll
        for (int mt = 0; mt < 2; mt++)
#pragma unroll
            for (int nt = 0; nt < 4; nt++)
#pragma unroll
                for (int c = 0; c < 4; c++) acc[mt][nt][c] = 0.f;

        fill_slab(sb, 0, 0, row0, n0, tid);
        cp_commit();
        fill_slab(sb, 1, 1, row0, n0, tid);
        cp_commit();
        fill_slab(sb, 2, 2, row0, n0, tid);
        cp_commit();

        int st = 0;
#pragma unroll 1
        for (int s = 0; s < 32; s++) {
            if (s <= 29) {
                cp_wait<2>();
            } else if (s == 30) {
                cp_wait<1>();
            } else {
                cp_wait<0>();
            }
            __syncthreads();  // single barrier per slab

            if (s < 29) {
                fill_slab(sb, (st + 3) & 3, s + 3, row0, n0, tid);
                cp_commit();
            }

            const uint32_t abase = sb + (uint32_t)(st * STAGE);
            const uint32_t bbase = abase + (uint32_t)(2 * PLANE);
#pragma unroll
            for (int ks = 0; ks < 2; ks++) {
                uint32_t ah[2][4], al[2][4];
#pragma unroll
                for (int mt = 0; mt < 2; mt++) {
                    uint32_t ra = abase + (a_row + mt * 16) * 80 + a_col + ks * 32;
                    ldsm_x4(ra, ah[mt][0], ah[mt][1], ah[mt][2], ah[mt][3]);
                    ldsm_x4(ra + PLANE, al[mt][0], al[mt][1], al[mt][2], al[mt][3]);
                }
#pragma unroll
                for (int q = 0; q < 2; q++) {
                    uint32_t bm[2][2];
                    {
                        uint32_t rb = bbase + (b_row + q * 16) * 80 + b_col + ks * 32;
                        uint32_t r0, r1, r2, r3;
                        ldsm_x4(rb, r0, r1, r2, r3);
                        bm[0][0] = r0; bm[0][1] = r1;
                        bm[1][0] = r2; bm[1][1] = r3;
                    }
#pragma unroll
                    for (int mt = 0; mt < 2; mt++)
#pragma unroll
                        for (int j = 0; j < 2; j++) {
                            mma_f32(acc[mt][2 * q + j], ah[mt], bm[j]);
                            mma_f32(acc[mt][2 * q + j], al[mt], bm[j]);
                        }
                }
            }
            st = (st + 1) & 3;
        }

        // Epilogue: msum += v[d]*tanh(acc + dec[d])
#pragma unroll
        for (int nt = 0; nt < 4; nt++) {
#pragma unroll
            for (int j = 0; j < 2; j++) {
                int d = n0 + wn * 32 + nt * 8 + 2 * (lane & 3) + j;
                float vd = v_s[d];
                float dj = dec_s[d];
#pragma unroll
                for (int mt = 0; mt < 2; mt++) {
#pragma unroll
                    for (int h = 0; h < 2; h++) {
                        float x = acc[mt][nt][h * 2 + j] + dj;
                        msum[mt * 2 + h] += vd * fast_tanh(x);
                    }
                }
            }
        }
    }

    // Cross-warp reduction
    float* red = (float*)(smem + RED_OFF);
    __syncthreads();
#pragma unroll
    for (int mt = 0; mt < 2; mt++)
#pragma unroll
        for (int h = 0; h < 2; h++) {
            int m = wm * 32 + mt * 16 + h * 8 + (lane >> 2);
            red[m * 16 + wn * 4 + (lane & 3)] = msum[mt * 2 + h];
        }
    __syncthreads();
    if (tid < 128) {
        float sum = 0.f;
#pragma unroll
        for (int x = 0; x < 16; x++) sum += red[tid * 16 + x];
        g_scores[row0 + tid] = sum;
    }
}

// ---------------------------------------------------------------------------
// Kernel 3: softmax over T per batch (in-place on g_scores)
// ---------------------------------------------------------------------------
__global__ void softmax_kernel() {
    const int b = blockIdx.x;
    const int tid = threadIdx.x;  // 256
    __shared__ float sred[256];
    float* sc = g_scores + b * TT;

    float vals[8];
    float mx = -INFINITY;
#pragma unroll
    for (int i = 0; i < 8; i++) {
        vals[i] = sc[tid + i * 256];
        mx = fmaxf(mx, vals[i]);
    }
    sred[tid] = mx;
    __syncthreads();
    for (int s = 128; s > 0; s >>= 1) {
        if (tid < s) sred[tid] = fmaxf(sred[tid], sred[tid + s]);
        __syncthreads();
    }
    mx = sred[0];
    __syncthreads();

    float sum = 0.f;
#pragma unroll
    for (int i = 0; i < 8; i++) {
        vals[i] = __expf(vals[i] - mx);
        sum += vals[i];
    }
    sred[tid] = sum;
    __syncthreads();
    for (int s = 128; s > 0; s >>= 1) {
        if (tid < s) sred[tid] += sred[tid + s];
        __syncthreads();
    }
    float inv = 1.0f / sred[0];
#pragma unroll
    for (int i = 0; i < 8; i++) sc[tid + i * 256] = vals[i] * inv;
}

// ---------------------------------------------------------------------------
// Zero init of ct_d region (d_out is poisoned to 0xAA)
// ---------------------------------------------------------------------------
__global__ void zero_ct(float* __restrict__ out) {
    int i = blockIdx.x * blockDim.x + threadIdx.x;
    reinterpret_cast<float4*>(out)[i] = make_float4(0.f, 0.f, 0.f, 0.f);
}

// ---------------------------------------------------------------------------
// Copy kernel (score-independent): prev_s_new = concat(prev_s, s_t).
// Runs on side stream, overlapping the score GEMM.
// ---------------------------------------------------------------------------
__global__ void copy_kernel(const float* __restrict__ prev_s,
                            const float* __restrict__ s_t,
                            float* __restrict__ out) {
    const int b = blockIdx.y;
    const int chunk = blockIdx.x;
    const int tid = threadIdx.x;
    float* pn = out + BB * HH;

    if (chunk == 16) {
        float4 sv = reinterpret_cast<const float4*>(s_t + (size_t)b * HH)[tid];
        reinterpret_cast<float4*>(pn + ((size_t)b * (TT + 1) + TT) * HH)[tid] = sv;
        return;
    }
    const int t0 = chunk * 128;
    const float4* src =
        reinterpret_cast<const float4*>(prev_s + ((size_t)b * TT + t0) * HH);
    float4* dst =
        reinterpret_cast<float4*>(pn + ((size_t)b * (TT + 1) + t0) * HH);
#pragma unroll 4
    for (int t = 0; t < 128; t++)
        dst[(size_t)t * 256 + tid] = src[(size_t)t * 256 + tid];
}

// ---------------------------------------------------------------------------
// ct kernel (needs softmax): ct_d[b,h] = sum_t a[b,t]*prev_s[b,t,h]
// ---------------------------------------------------------------------------
__global__ void ct_kernel(const float* __restrict__ prev_s,
                          float* __restrict__ out) {
    const int b = blockIdx.y;
    const int t0 = blockIdx.x * 128;
    const int tid = threadIdx.x;
    const float4* src =
        reinterpret_cast<const float4*>(prev_s + ((size_t)b * TT + t0) * HH);
    const float* __restrict__ a = g_scores + b * TT + t0;

    float4 acc = make_float4(0.f, 0.f, 0.f, 0.f);
#pragma unroll 4
    for (int t = 0; t < 128; t++) {
        float4 p = src[(size_t)t * 256 + tid];
        float at = __ldg(&a[t]);
        acc.x += at * p.x;
        acc.y += at * p.y;
        acc.z += at * p.z;
        acc.w += at * p.w;
    }
    float* ctb = out + (size_t)b * HH + tid * 4;
    atomicAdd(ctb + 0, acc.x);
    atomicAdd(ctb + 1, acc.y);
    atomicAdd(ctb + 2, acc.z);
    atomicAdd(ctb + 3, acc.w);
}

// ---------------------------------------------------------------------------
extern "C" void kernel_launch(void* const* d_in, const int* in_sizes, int n_in,
                              void* d_out, int out_size) {
    const float* s_t    = (const float*)d_in[0];
    const float* prev_s = (const float*)d_in[1];
    const float* W_prev = (const float*)d_in[2];
    const float* W_s    = (const float*)d_in[3];
    const float* b_s    = (const float*)d_in[4];
    const float* v      = (const float*)d_in[5];
    float* out = (float*)d_out;

    static cudaStream_t s2 = nullptr;
    static cudaEvent_t ev_fork = nullptr, ev_join = nullptr;
    if (!s2) {
        cudaStreamCreateWithFlags(&s2, cudaStreamNonBlocking);
        cudaEventCreateWithFlags(&ev_fork, cudaEventDisableTiming);
        cudaEventCreateWithFlags(&ev_join, cudaEventDisableTiming);
        cudaFuncSetAttribute(score_kernel,
                             cudaFuncAttributeMaxDynamicSharedMemorySize, SMEM_BYTES);
    }

    __half *gA, *gB;
    cudaGetSymbolAddress((void**)&gA, g_A);
    cudaGetSymbolAddress((void**)&gB, g_B);

    // Fork: side stream does zero_ct + the big prev_s_new copy, overlapping
    // the main stream's prepack + score GEMM (whose DRAM util is ~3%).
    cudaEventRecord(ev_fork, 0);
    cudaStreamWaitEvent(s2, ev_fork, 0);
    zero_ct<<<32, 256, 0, s2>>>(out);
    dim3 gc(17, BB);
    copy_kernel<<<gc, 256, 0, s2>>>(prev_s, s_t, out);
    cudaEventRecord(ev_join, s2);

    // Main stream: prepack -> dec_fea -> score -> softmax
    conv_b_kernel<<<512, 256>>>(W_prev, gB);
    conv_split_kernel<<<32768, 256>>>(prev_s, gA);
    dec_fea_kernel<<<HH / 128, 256>>>(s_t, W_s, b_s);
    score_kernel<<<(BB * TT) / 128, 512, SMEM_BYTES>>>(v);
    softmax_kernel<<<BB, 256>>>();

    // Join: ct needs zero_ct done (atomics into the zeroed region)
    cudaStreamWaitEvent(0, ev_join, 0);
    dim3 gt(16, BB);
    ct_kernel<<<gt, 256>>>(prev_s, out);
}

// round 9
// speedup vs baseline: 1.0198x; 1.0198x over previous
#include <cuda_runtime.h>
#include <cuda_fp16.h>
#include <math.h>
#include <cstdint>

#define BB 32
#define TT 2048
#define HH 1024

// Scratch (allocation-free rule: __device__ globals)
__device__ float g_decfea[BB * HH];
__device__ float g_scores[BB * TT];
__device__ __half g_B[(size_t)HH * HH];            // W_prev fp16 (2 MB), plain
// A split planes: per 32-k slab of each row: [32 hi | 32 lo] fp16 = 128B
__device__ __half g_A[(size_t)BB * TT * HH * 2];   // prev_s (268 MB)

// ---------------------------------------------------------------------------
// PTX helpers
// ---------------------------------------------------------------------------
__device__ __forceinline__ uint32_t smem_u32(const void* p) {
    uint32_t a;
    asm("{ .reg .u64 t; cvta.to.shared.u64 t, %1; cvt.u32.u64 %0, t; }" : "=r"(a) : "l"(p));
    return a;
}
__device__ __forceinline__ void cp_async16(uint32_t dst, const void* src) {
    asm volatile("cp.async.cg.shared.global [%0], [%1], 16;" :: "r"(dst), "l"(src) : "memory");
}
__device__ __forceinline__ void cp_commit() {
    asm volatile("cp.async.commit_group;" ::: "memory");
}
template <int N>
__device__ __forceinline__ void cp_wait() {
    asm volatile("cp.async.wait_group %0;" :: "n"(N) : "memory");
}
__device__ __forceinline__ void ldsm_x4(uint32_t addr, uint32_t& r0, uint32_t& r1,
                                        uint32_t& r2, uint32_t& r3) {
    asm volatile("ldmatrix.sync.aligned.m8n8.x4.shared.b16 {%0,%1,%2,%3}, [%4];"
                 : "=r"(r0), "=r"(r1), "=r"(r2), "=r"(r3) : "r"(addr));
}
__device__ __forceinline__ void mma_f32(float* c, const uint32_t* a, const uint32_t* b) {
    asm volatile(
        "mma.sync.aligned.m16n8k16.row.col.f32.f16.f16.f32 "
        "{%0,%1,%2,%3}, {%4,%5,%6,%7}, {%8,%9}, {%0,%1,%2,%3};"
        : "+f"(c[0]), "+f"(c[1]), "+f"(c[2]), "+f"(c[3])
        : "r"(a[0]), "r"(a[1]), "r"(a[2]), "r"(a[3]), "r"(b[0]), "r"(b[1]));
}
__device__ __forceinline__ float fast_tanh(float x) {
    float y;
    asm("tanh.approx.f32 %0, %1;" : "=f"(y) : "f"(x));
    return y;
}
__device__ __forceinline__ uint32_t pack_h2(__half a, __half b) {
    __half2 t = __halves2half2(a, b);
    return *reinterpret_cast<uint32_t*>(&t);
}
// fp16 split, UNSCALED residual: hi = f16(x), lo = f16(x - hi).
__device__ __forceinline__ void split2h(float x, float y, uint32_t& hi, uint32_t& lo) {
    __half hx = __float2half_rn(x), hy = __float2half_rn(y);
    __half lx = __float2half_rn(x - __half2float(hx));
    __half ly = __float2half_rn(y - __half2float(hy));
    hi = pack_h2(hx, hy);
    lo = pack_h2(lx, ly);
}

// ---------------------------------------------------------------------------
// A prepack: fp32 rows -> [32 hi | 32 lo] fp16 per 32-k slab.
// ---------------------------------------------------------------------------
__global__ void conv_split_kernel(const float* __restrict__ src,
                                  __half* __restrict__ dst) {
    size_t t = (size_t)blockIdx.x * 256 + threadIdx.x;
    int j = (int)(t & 3);
    size_t chunk = t >> 2;  // row*32 + slab
    const float* s = src + chunk * 32 + (size_t)j * 8;
    float4 f0 = *(const float4*)s;
    float4 f1 = *(const float4*)(s + 4);
    uint4 hi, lo;
    split2h(f0.x, f0.y, hi.x, lo.x);
    split2h(f0.z, f0.w, hi.y, lo.y);
    split2h(f1.x, f1.y, hi.z, lo.z);
    split2h(f1.z, f1.w, hi.w, lo.w);
    __half* d = dst + chunk * 64;
    *(uint4*)(d + j * 8) = hi;
    *(uint4*)(d + 32 + j * 8) = lo;
}

// B prepack: plain fp32 -> fp16 (row-major, k contiguous)
__global__ void conv_b_kernel(const float* __restrict__ src,
                              __half* __restrict__ dst) {
    size_t t = (size_t)blockIdx.x * 256 + threadIdx.x;  // x8 elems
    const float* s = src + t * 8;
    float4 f0 = *(const float4*)s;
    float4 f1 = *(const float4*)(s + 4);
    uint4 o;
    o.x = pack_h2(__float2half_rn(f0.x), __float2half_rn(f0.y));
    o.y = pack_h2(__float2half_rn(f0.z), __float2half_rn(f0.w));
    o.z = pack_h2(__float2half_rn(f1.x), __float2half_rn(f1.y));
    o.w = pack_h2(__float2half_rn(f1.z), __float2half_rn(f1.w));
    *(uint4*)(dst + t * 8) = o;
}

// ---------------------------------------------------------------------------
// Kernel 1: dec_fea[b,d] = sum_h s_t[b,h] * W_s[d,h] + b_s[d]   (fp32, small)
// ---------------------------------------------------------------------------
__global__ void dec_fea_kernel(const float* __restrict__ s_t,
                               const float* __restrict__ W_s,
                               const float* __restrict__ b_s) {
    __shared__ float Ss[32][BB + 1];
    __shared__ float Ws[32][128 + 1];
    const int d0 = blockIdx.x * 128;
    const int tid = threadIdx.x;
    const int dl = tid & 127;
    const int bq = tid >> 7;

    float acc[16];
#pragma unroll
    for (int i = 0; i < 16; i++) acc[i] = 0.f;

    for (int k0 = 0; k0 < HH; k0 += 32) {
        for (int i = tid; i < BB * 32; i += 256) {
            int bb = i >> 5, kk = i & 31;
            Ss[kk][bb] = s_t[bb * HH + k0 + kk];
        }
        for (int i = tid; i < 128 * 32; i += 256) {
            int dd = i >> 5, kk = i & 31;
            Ws[kk][dd] = W_s[(d0 + dd) * HH + k0 + kk];
        }
        __syncthreads();
#pragma unroll
        for (int kk = 0; kk < 32; kk++) {
            float w = Ws[kk][dl];
#pragma unroll
            for (int i = 0; i < 16; i++)
                acc[i] += w * Ss[kk][bq * 16 + i];
        }
        __syncthreads();
    }
    float bias = b_s[d0 + dl];
#pragma unroll
    for (int i = 0; i < 16; i++)
        g_decfea[(bq * 16 + i) * HH + d0 + dl] = acc[i] + bias;
}

// ---------------------------------------------------------------------------
// Kernel 2: fused score GEMM, fp16x2 split-A mma.sync (both passes f32-acc).
// CTA: 128 M x (8 n-chunks of 128), 4-stage cp.async ring, 1 barrier/slab.
// 16 warps = 4(m) x 4(n); warp tile 32m x 32n; SMEM rows padded to 80B.
// ---------------------------------------------------------------------------
constexpr int PLANE = 10240;        // 128 rows * 80B
constexpr int STAGE = 30720;        // A hi + A lo + B (one plane each)
constexpr int NSTAGE = 4;
constexpr int V_OFF = STAGE * NSTAGE;          // 122880
constexpr int DEC_OFF = V_OFF + 4096;
constexpr int RED_OFF = DEC_OFF + 4096;
constexpr int SMEM_BYTES = RED_OFF + 8192;     // 139264

__device__ __forceinline__ void fill_slab(uint32_t sb, int st, int s,
                                          int row0, int n0, int tid) {
#pragma unroll
    for (int it = 0; it < 3; it++) {
        int idx = tid + it * 512;           // 0..1535
        if (idx < 1024) {
            int m = idx >> 3;
            int p = (idx >> 2) & 1;
            int c = idx & 3;
            const __half* src =
                g_A + ((size_t)(row0 + m) * 32 + s) * 64 + p * 32 + c * 8;
            uint32_t dst = sb + (uint32_t)(st * STAGE) + p * PLANE + m * 80 + c * 16;
            cp_async16(dst, src);
        } else {
            int loc = idx - 1024;
            int m = loc >> 2;
            int c = loc & 3;
            const __half* src = g_B + (size_t)(n0 + m) * HH + s * 32 + c * 8;
            uint32_t dst = sb + (uint32_t)(st * STAGE) + 2 * PLANE + m * 80 + c * 16;
            cp_async16(dst, src);
        }
    }
}

__global__ void __launch_bounds__(512, 1)
score_kernel(const float* __restrict__ vvec) {
    extern __shared__ char smem[];
    const uint32_t sb = smem_u32(smem);
    const int tid = threadIdx.x;
    const int warp = tid >> 5;
    const int lane = tid & 31;
    const int wm = warp >> 2;   // 0..3
    const int wn = warp & 3;    // 0..3
    const int row0 = blockIdx.x * 128;
    const int b = blockIdx.x >> 4;

    float* v_s = (float*)(smem + V_OFF);
    float* dec_s = (float*)(smem + DEC_OFF);
    for (int i = tid; i < 1024; i += 512) {
        v_s[i] = vvec[i];
        dec_s[i] = g_decfea[b * 1024 + i];
    }
    __syncthreads();

    const int a_row = wm * 32 + (lane & 15);                    // + mt*16
    const int a_col = ((lane >> 4) << 4);                       // 0 or 16 bytes
    const int b_row = wn * 32 + (((lane >> 4) & 1) << 3) + (lane & 7);  // + q*16
    const int b_col = (((lane >> 3) & 1) << 4);

    float msum[4];
#pragma unroll
    for (int i = 0; i < 4; i++) msum[i] = 0.f;

#pragma unroll 1
    for (int nc = 0; nc < 8; nc++) {
        const int n0 = nc * 128;
        float acc[2][4][4];
#pragma unroll
        for (int mt = 0; mt < 2; mt++)
#pragma unroll
            for (int nt = 0; nt < 4; nt++)
#pragma unroll
                for (int c = 0; c < 4; c++) acc[mt][nt][c] = 0.f;

        fill_slab(sb, 0, 0, row0, n0, tid);
        cp_commit();
        fill_slab(sb, 1, 1, row0, n0, tid);
        cp_commit();
        fill_slab(sb, 2, 2, row0, n0, tid);
        cp_commit();

        int st = 0;
#pragma unroll 1
        for (int s = 0; s < 32; s++) {
            if (s <= 29) {
                cp_wait<2>();
            } else if (s == 30) {
                cp_wait<1>();
            } else {
                cp_wait<0>();
            }
            __syncthreads();  // single barrier per slab

            if (s < 29) {
                fill_slab(sb, (st + 3) & 3, s + 3, row0, n0, tid);
                cp_commit();
            }

            const uint32_t abase = sb + (uint32_t)(st * STAGE);
            const uint32_t bbase = abase + (uint32_t)(2 * PLANE);
#pragma unroll
            for (int ks = 0; ks < 2; ks++) {
                uint32_t ah[2][4], al[2][4];
#pragma unroll
                for (int mt = 0; mt < 2; mt++) {
                    uint32_t ra = abase + (a_row + mt * 16) * 80 + a_col + ks * 32;
                    ldsm_x4(ra, ah[mt][0], ah[mt][1], ah[mt][2], ah[mt][3]);
                    ldsm_x4(ra + PLANE, al[mt][0], al[mt][1], al[mt][2], al[mt][3]);
                }
#pragma unroll
                for (int q = 0; q < 2; q++) {
                    uint32_t bm[2][2];
                    {
                        uint32_t rb = bbase + (b_row + q * 16) * 80 + b_col + ks * 32;
                        uint32_t r0, r1, r2, r3;
                        ldsm_x4(rb, r0, r1, r2, r3);
                        bm[0][0] = r0; bm[0][1] = r1;
                        bm[1][0] = r2; bm[1][1] = r3;
                    }
#pragma unroll
                    for (int mt = 0; mt < 2; mt++)
#pragma unroll
                        for (int j = 0; j < 2; j++) {
                            mma_f32(acc[mt][2 * q + j], ah[mt], bm[j]);
                            mma_f32(acc[mt][2 * q + j], al[mt], bm[j]);
                        }
                }
            }
            st = (st + 1) & 3;
        }

        // Epilogue: msum += v[d]*tanh(acc + dec[d])
#pragma unroll
        for (int nt = 0; nt < 4; nt++) {
#pragma unroll
            for (int j = 0; j < 2; j++) {
                int d = n0 + wn * 32 + nt * 8 + 2 * (lane & 3) + j;
                float vd = v_s[d];
                float dj = dec_s[d];
#pragma unroll
                for (int mt = 0; mt < 2; mt++) {
#pragma unroll
                    for (int h = 0; h < 2; h++) {
                        float x = acc[mt][nt][h * 2 + j] + dj;
                        msum[mt * 2 + h] += vd * fast_tanh(x);
                    }
                }
            }
        }
    }

    // Cross-warp reduction
    float* red = (float*)(smem + RED_OFF);
    __syncthreads();
#pragma unroll
    for (int mt = 0; mt < 2; mt++)
#pragma unroll
        for (int h = 0; h < 2; h++) {
            int m = wm * 32 + mt * 16 + h * 8 + (lane >> 2);
            red[m * 16 + wn * 4 + (lane & 3)] = msum[mt * 2 + h];
        }
    __syncthreads();
    if (tid < 128) {
        float sum = 0.f;
#pragma unroll
        for (int x = 0; x < 16; x++) sum += red[tid * 16 + x];
        g_scores[row0 + tid] = sum;
    }
}

// ---------------------------------------------------------------------------
// Kernel 3: softmax over T per batch (in-place on g_scores)
// ---------------------------------------------------------------------------
__global__ void softmax_kernel() {
    const int b = blockIdx.x;
    const int tid = threadIdx.x;  // 256
    __shared__ float sred[256];
    float* sc = g_scores + b * TT;

    float vals[8];
    float mx = -INFINITY;
#pragma unroll
    for (int i = 0; i < 8; i++) {
        vals[i] = sc[tid + i * 256];
        mx = fmaxf(mx, vals[i]);
    }
    sred[tid] = mx;
    __syncthreads();
    for (int s = 128; s > 0; s >>= 1) {
        if (tid < s) sred[tid] = fmaxf(sred[tid], sred[tid + s]);
        __syncthreads();
    }
    mx = sred[0];
    __syncthreads();

    float sum = 0.f;
#pragma unroll
    for (int i = 0; i < 8; i++) {
        vals[i] = __expf(vals[i] - mx);
        sum += vals[i];
    }
    sred[tid] = sum;
    __syncthreads();
    for (int s = 128; s > 0; s >>= 1) {
        if (tid < s) sred[tid] += sred[tid + s];
        __syncthreads();
    }
    float inv = 1.0f / sred[0];
#pragma unroll
    for (int i = 0; i < 8; i++) sc[tid + i * 256] = vals[i] * inv;
}

// ---------------------------------------------------------------------------
// Zero init of ct_d region (d_out is poisoned to 0xAA)
// ---------------------------------------------------------------------------
__global__ void zero_ct(float* __restrict__ out) {
    int i = blockIdx.x * blockDim.x + threadIdx.x;
    reinterpret_cast<float4*>(out)[i] = make_float4(0.f, 0.f, 0.f, 0.f);
}

// ---------------------------------------------------------------------------
// Copy kernel (score-independent): prev_s_new = concat(prev_s, s_t).
// Runs on side stream AFTER conv prepack, overlapping the score GEMM
// (which sits at ~3.5% DRAM).
// ---------------------------------------------------------------------------
__global__ void copy_kernel(const float* __restrict__ prev_s,
                            const float* __restrict__ s_t,
                            float* __restrict__ out) {
    const int b = blockIdx.y;
    const int chunk = blockIdx.x;
    const int tid = threadIdx.x;
    float* pn = out + BB * HH;

    if (chunk == 16) {
        float4 sv = reinterpret_cast<const float4*>(s_t + (size_t)b * HH)[tid];
        reinterpret_cast<float4*>(pn + ((size_t)b * (TT + 1) + TT) * HH)[tid] = sv;
        return;
    }
    const int t0 = chunk * 128;
    const float4* src =
        reinterpret_cast<const float4*>(prev_s + ((size_t)b * TT + t0) * HH);
    float4* dst =
        reinterpret_cast<float4*>(pn + ((size_t)b * (TT + 1) + t0) * HH);
#pragma unroll 4
    for (int t = 0; t < 128; t++)
        dst[(size_t)t * 256 + tid] = src[(size_t)t * 256 + tid];
}

// ---------------------------------------------------------------------------
// ct kernel (needs softmax): ct_d[b,h] = sum_t a[b,t]*prev_s[b,t,h]
// ---------------------------------------------------------------------------
__global__ void ct_kernel(const float* __restrict__ prev_s,
                          float* __restrict__ out) {
    const int b = blockIdx.y;
    const int t0 = blockIdx.x * 128;
    const int tid = threadIdx.x;
    const float4* src =
        reinterpret_cast<const float4*>(prev_s + ((size_t)b * TT + t0) * HH);
    const float* __restrict__ a = g_scores + b * TT + t0;

    float4 acc = make_float4(0.f, 0.f, 0.f, 0.f);
#pragma unroll 4
    for (int t = 0; t < 128; t++) {
        float4 p = src[(size_t)t * 256 + tid];
        float at = __ldg(&a[t]);
        acc.x += at * p.x;
        acc.y += at * p.y;
        acc.z += at * p.z;
        acc.w += at * p.w;
    }
    float* ctb = out + (size_t)b * HH + tid * 4;
    atomicAdd(ctb + 0, acc.x);
    atomicAdd(ctb + 1, acc.y);
    atomicAdd(ctb + 2, acc.z);
    atomicAdd(ctb + 3, acc.w);
}

// ---------------------------------------------------------------------------
extern "C" void kernel_launch(void* const* d_in, const int* in_sizes, int n_in,
                              void* d_out, int out_size) {
    const float* s_t    = (const float*)d_in[0];
    const float* prev_s = (const float*)d_in[1];
    const float* W_prev = (const float*)d_in[2];
    const float* W_s    = (const float*)d_in[3];
    const float* b_s    = (const float*)d_in[4];
    const float* v      = (const float*)d_in[5];
    float* out = (float*)d_out;

    static cudaStream_t s2 = nullptr;
    static cudaEvent_t ev_fork = nullptr, ev_join = nullptr;
    if (!s2) {
        cudaStreamCreateWithFlags(&s2, cudaStreamNonBlocking);
        cudaEventCreateWithFlags(&ev_fork, cudaEventDisableTiming);
        cudaEventCreateWithFlags(&ev_join, cudaEventDisableTiming);
        cudaFuncSetAttribute(score_kernel,
                             cudaFuncAttributeMaxDynamicSharedMemorySize, SMEM_BYTES);
    }

    __half *gA, *gB;
    cudaGetSymbolAddress((void**)&gA, g_A);
    cudaGetSymbolAddress((void**)&gB, g_B);

    // Phase 1 (main stream): DRAM-bound prepack — run alone at full bandwidth.
    conv_b_kernel<<<512, 256>>>(W_prev, gB);
    conv_split_kernel<<<32768, 256>>>(prev_s, gA);

    // Fork AFTER prepack: side stream does zero_ct + prev_s_new copy while
    // the main stream runs the compute-bound score GEMM (DRAM ~3.5% there).
    cudaEventRecord(ev_fork, 0);
    cudaStreamWaitEvent(s2, ev_fork, 0);
    zero_ct<<<32, 256, 0, s2>>>(out);
    dim3 gc(17, BB);
    copy_kernel<<<gc, 256, 0, s2>>>(prev_s, s_t, out);
    cudaEventRecord(ev_join, s2);

    // Main stream: dec_fea -> score -> softmax
    dec_fea_kernel<<<HH / 128, 256>>>(s_t, W_s, b_s);
    score_kernel<<<(BB * TT) / 128, 512, SMEM_BYTES>>>(v);
    softmax_kernel<<<BB, 256>>>();

    // Join: ct atomics need zero_ct (and copy done before return).
    cudaStreamWaitEvent(0, ev_join, 0);
    dim3 gt(16, BB);
    ct_kernel<<<gt, 256>>>(prev_s, out);
}

// round 10
// speedup vs baseline: 1.0243x; 1.0044x over previous
#include <cuda_runtime.h>
#include <cuda_fp16.h>
#include <math.h>
#include <cstdint>

#define BB 32
#define TT 2048
#define HH 1024

// Scratch (allocation-free rule: __device__ globals)
__device__ float g_decfea[BB * HH];
__device__ float g_scores[BB * TT];
__device__ __half g_B[(size_t)HH * HH];            // W_prev fp16 (2 MB), plain
// A split planes: per 32-k slab of each row: [32 hi | 32 lo] fp16 = 128B
__device__ __half g_A[(size_t)BB * TT * HH * 2];   // prev_s (268 MB)

// ---------------------------------------------------------------------------
// PTX helpers
// ---------------------------------------------------------------------------
__device__ __forceinline__ uint32_t smem_u32(const void* p) {
    uint32_t a;
    asm("{ .reg .u64 t; cvta.to.shared.u64 t, %1; cvt.u32.u64 %0, t; }" : "=r"(a) : "l"(p));
    return a;
}
__device__ __forceinline__ void cp_async16(uint32_t dst, const void* src) {
    asm volatile("cp.async.cg.shared.global [%0], [%1], 16;" :: "r"(dst), "l"(src) : "memory");
}
__device__ __forceinline__ void cp_commit() {
    asm volatile("cp.async.commit_group;" ::: "memory");
}
template <int N>
__device__ __forceinline__ void cp_wait() {
    asm volatile("cp.async.wait_group %0;" :: "n"(N) : "memory");
}
__device__ __forceinline__ void ldsm_x4(uint32_t addr, uint32_t& r0, uint32_t& r1,
                                        uint32_t& r2, uint32_t& r3) {
    asm volatile("ldmatrix.sync.aligned.m8n8.x4.shared.b16 {%0,%1,%2,%3}, [%4];"
                 : "=r"(r0), "=r"(r1), "=r"(r2), "=r"(r3) : "r"(addr));
}
__device__ __forceinline__ void mma_f32(float* c, const uint32_t* a, const uint32_t* b) {
    asm volatile(
        "mma.sync.aligned.m16n8k16.row.col.f32.f16.f16.f32 "
        "{%0,%1,%2,%3}, {%4,%5,%6,%7}, {%8,%9}, {%0,%1,%2,%3};"
        : "+f"(c[0]), "+f"(c[1]), "+f"(c[2]), "+f"(c[3])
        : "r"(a[0]), "r"(a[1]), "r"(a[2]), "r"(a[3]), "r"(b[0]), "r"(b[1]));
}
__device__ __forceinline__ float fast_tanh(float x) {
    float y;
    asm("tanh.approx.f32 %0, %1;" : "=f"(y) : "f"(x));
    return y;
}
__device__ __forceinline__ uint32_t pack_h2(__half a, __half b) {
    __half2 t = __halves2half2(a, b);
    return *reinterpret_cast<uint32_t*>(&t);
}
// fp16 split, UNSCALED residual: hi = f16(x), lo = f16(x - hi).
__device__ __forceinline__ void split2h(float x, float y, uint32_t& hi, uint32_t& lo) {
    __half hx = __float2half_rn(x), hy = __float2half_rn(y);
    __half lx = __float2half_rn(x - __half2float(hx));
    __half ly = __float2half_rn(y - __half2float(hy));
    hi = pack_h2(hx, hy);
    lo = pack_h2(lx, ly);
}

// ---------------------------------------------------------------------------
// A prepack + concat copy fused: reads prev_s once, writes split fp16 planes
// to g_A AND the raw fp32 row into out's prev_s_new region.
// ---------------------------------------------------------------------------
__global__ void conv_split_copy_kernel(const float* __restrict__ src,
                                       __half* __restrict__ dst,
                                       float* __restrict__ out) {
    size_t t = (size_t)blockIdx.x * 256 + threadIdx.x;
    int j = (int)(t & 3);
    size_t chunk = t >> 2;          // row*32 + slab
    int slab = (int)(chunk & 31);
    size_t row = chunk >> 5;        // 0..65535 = b*2048 + tt
    int b = (int)(row >> 11);
    int tt = (int)(row & 2047);

    const float* s = src + chunk * 32 + (size_t)j * 8;
    float4 f0 = *(const float4*)s;
    float4 f1 = *(const float4*)(s + 4);
    uint4 hi, lo;
    split2h(f0.x, f0.y, hi.x, lo.x);
    split2h(f0.z, f0.w, hi.y, lo.y);
    split2h(f1.x, f1.y, hi.z, lo.z);
    split2h(f1.z, f1.w, hi.w, lo.w);
    __half* d = dst + chunk * 64;
    *(uint4*)(d + j * 8) = hi;
    *(uint4*)(d + 32 + j * 8) = lo;

    // concat copy: prev_s_new[b, tt, :] = prev_s[b, tt, :]
    float* o = out + (size_t)BB * HH +
               ((size_t)b * (TT + 1) + tt) * HH + slab * 32 + j * 8;
    *(float4*)o = f0;
    *(float4*)(o + 4) = f1;
}

// B prepack: plain fp32 -> fp16 (row-major, k contiguous)
__global__ void conv_b_kernel(const float* __restrict__ src,
                              __half* __restrict__ dst) {
    size_t t = (size_t)blockIdx.x * 256 + threadIdx.x;  // x8 elems
    const float* s = src + t * 8;
    float4 f0 = *(const float4*)s;
    float4 f1 = *(const float4*)(s + 4);
    uint4 o;
    o.x = pack_h2(__float2half_rn(f0.x), __float2half_rn(f0.y));
    o.y = pack_h2(__float2half_rn(f0.z), __float2half_rn(f0.w));
    o.z = pack_h2(__float2half_rn(f1.x), __float2half_rn(f1.y));
    o.w = pack_h2(__float2half_rn(f1.z), __float2half_rn(f1.w));
    *(uint4*)(dst + t * 8) = o;
}

// ---------------------------------------------------------------------------
// Init kernel: zero ct_d region + write the s_t concat row.
// 64 blocks x 256 threads x float4: idx<8192 -> zero; else s_t row copy.
// ---------------------------------------------------------------------------
__global__ void init_kernel(const float* __restrict__ s_t,
                            float* __restrict__ out) {
    int idx = blockIdx.x * 256 + threadIdx.x;   // 0..16383 (float4 units)
    if (idx < 8192) {
        reinterpret_cast<float4*>(out)[idx] = make_float4(0.f, 0.f, 0.f, 0.f);
    } else {
        int i = idx - 8192;                      // 0..8191 = b*256 + c
        int b = i >> 8, c = i & 255;
        float4 sv = reinterpret_cast<const float4*>(s_t + (size_t)b * HH)[c];
        float* pn = out + BB * HH + ((size_t)b * (TT + 1) + TT) * HH;
        reinterpret_cast<float4*>(pn)[c] = sv;
    }
}

// ---------------------------------------------------------------------------
// Kernel 1: dec_fea[b,d] = sum_h s_t[b,h] * W_s[d,h] + b_s[d]   (fp32, small)
// ---------------------------------------------------------------------------
__global__ void dec_fea_kernel(const float* __restrict__ s_t,
                               const float* __restrict__ W_s,
                               const float* __restrict__ b_s) {
    __shared__ float Ss[32][BB + 1];
    __shared__ float Ws[32][128 + 1];
    const int d0 = blockIdx.x * 128;
    const int tid = threadIdx.x;
    const int dl = tid & 127;
    const int bq = tid >> 7;

    float acc[16];
#pragma unroll
    for (int i = 0; i < 16; i++) acc[i] = 0.f;

    for (int k0 = 0; k0 < HH; k0 += 32) {
        for (int i = tid; i < BB * 32; i += 256) {
            int bb = i >> 5, kk = i & 31;
            Ss[kk][bb] = s_t[bb * HH + k0 + kk];
        }
        for (int i = tid; i < 128 * 32; i += 256) {
            int dd = i >> 5, kk = i & 31;
            Ws[kk][dd] = W_s[(d0 + dd) * HH + k0 + kk];
        }
        __syncthreads();
#pragma unroll
        for (int kk = 0; kk < 32; kk++) {
            float w = Ws[kk][dl];
#pragma unroll
            for (int i = 0; i < 16; i++)
                acc[i] += w * Ss[kk][bq * 16 + i];
        }
        __syncthreads();
    }
    float bias = b_s[d0 + dl];
#pragma unroll
    for (int i = 0; i < 16; i++)
        g_decfea[(bq * 16 + i) * HH + d0 + dl] = acc[i] + bias;
}

// ---------------------------------------------------------------------------
// Kernel 2: fused score GEMM, fp16x2 split-A mma.sync (both passes f32-acc).
// CTA: 128 M x (8 n-chunks of 128), 4-stage cp.async ring, 1 barrier/slab.
// 16 warps = 4(m) x 4(n); warp tile 32m x 32n; SMEM rows padded to 80B.
// ---------------------------------------------------------------------------
constexpr int PLANE = 10240;        // 128 rows * 80B
constexpr int STAGE = 30720;        // A hi + A lo + B (one plane each)
constexpr int NSTAGE = 4;
constexpr int V_OFF = STAGE * NSTAGE;          // 122880
constexpr int DEC_OFF = V_OFF + 4096;
constexpr int RED_OFF = DEC_OFF + 4096;
constexpr int SMEM_BYTES = RED_OFF + 8192;     // 139264

__device__ __forceinline__ void fill_slab(uint32_t sb, int st, int s,
                                          int row0, int n0, int tid) {
#pragma unroll
    for (int it = 0; it < 3; it++) {
        int idx = tid + it * 512;           // 0..1535
        if (idx < 1024) {
            int m = idx >> 3;
            int p = (idx >> 2) & 1;
            int c = idx & 3;
            const __half* src =
                g_A + ((size_t)(row0 + m) * 32 + s) * 64 + p * 32 + c * 8;
            uint32_t dst = sb + (uint32_t)(st * STAGE) + p * PLANE + m * 80 + c * 16;
            cp_async16(dst, src);
        } else {
            int loc = idx - 1024;
            int m = loc >> 2;
            int c = loc & 3;
            const __half* src = g_B + (size_t)(n0 + m) * HH + s * 32 + c * 8;
            uint32_t dst = sb + (uint32_t)(st * STAGE) + 2 * PLANE + m * 80 + c * 16;
            cp_async16(dst, src);
        }
    }
}

__global__ void __launch_bounds__(512, 1)
score_kernel(const float* __restrict__ vvec) {
    extern __shared__ char smem[];
    const uint32_t sb = smem_u32(smem);
    const int tid = threadIdx.x;
    const int warp = tid >> 5;
    const int lane = tid & 31;
    const int wm = warp >> 2;   // 0..3
    const int wn = warp & 3;    // 0..3
    const int row0 = blockIdx.x * 128;
    const int b = blockIdx.x >> 4;

    float* v_s = (float*)(smem + V_OFF);
    float* dec_s = (float*)(smem + DEC_OFF);
    for (int i = tid; i < 1024; i += 512) {
        v_s[i] = vvec[i];
        dec_s[i] = g_decfea[b * 1024 + i];
    }
    __syncthreads();

    const int a_row = wm * 32 + (lane & 15);                    // + mt*16
    const int a_col = ((lane >> 4) << 4);                       // 0 or 16 bytes
    const int b_row = wn * 32 + (((lane >> 4) & 1) << 3) + (lane & 7);  // + q*16
    const int b_col = (((lane >> 3) & 1) << 4);

    float msum[4];
#pragma unroll
    for (int i = 0; i < 4; i++) msum[i] = 0.f;

#pragma unroll 1
    for (int nc = 0; nc < 8; nc++) {
        const int n0 = nc * 128;
        float acc[2][4][4];
#pragma unroll
        for (int mt = 0; mt < 2; mt++)
#pragma unroll
            for (int nt = 0; nt < 4; nt++)
#pragma unroll
                for (int c = 0; c < 4; c++) acc[mt][nt][c] = 0.f;

        fill_slab(sb, 0, 0, row0, n0, tid);
        cp_commit();
        fill_slab(sb, 1, 1, row0, n0, tid);
        cp_commit();
        fill_slab(sb, 2, 2, row0, n0, tid);
        cp_commit();

        int st = 0;
#pragma unroll 1
        for (int s = 0; s < 32; s++) {
            if (s <= 29) {
                cp_wait<2>();
            } else if (s == 30) {
                cp_wait<1>();
            } else {
                cp_wait<0>();
            }
            __syncthreads();  // single barrier per slab

            if (s < 29) {
                fill_slab(sb, (st + 3) & 3, s + 3, row0, n0, tid);
                cp_commit();
            }

            const uint32_t abase = sb + (uint32_t)(st * STAGE);
            const uint32_t bbase = abase + (uint32_t)(2 * PLANE);
#pragma unroll
            for (int ks = 0; ks < 2; ks++) {
                uint32_t ah[2][4], al[2][4];
#pragma unroll
                for (int mt = 0; mt < 2; mt++) {
                    uint32_t ra = abase + (a_row + mt * 16) * 80 + a_col + ks * 32;
                    ldsm_x4(ra, ah[mt][0], ah[mt][1], ah[mt][2], ah[mt][3]);
                    ldsm_x4(ra + PLANE, al[mt][0], al[mt][1], al[mt][2], al[mt][3]);
                }
#pragma unroll
                for (int q = 0; q < 2; q++) {
                    uint32_t bm[2][2];
                    {
                        uint32_t rb = bbase + (b_row + q * 16) * 80 + b_col + ks * 32;
                        uint32_t r0, r1, r2, r3;
                        ldsm_x4(rb, r0, r1, r2, r3);
                        bm[0][0] = r0; bm[0][1] = r1;
                        bm[1][0] = r2; bm[1][1] = r3;
                    }
#pragma unroll
                    for (int mt = 0; mt < 2; mt++)
#pragma unroll
                        for (int j = 0; j < 2; j++) {
                            mma_f32(acc[mt][2 * q + j], ah[mt], bm[j]);
                            mma_f32(acc[mt][2 * q + j], al[mt], bm[j]);
                        }
                }
            }
            st = (st + 1) & 3;
        }

        // Epilogue: msum += v[d]*tanh(acc + dec[d])
#pragma unroll
        for (int nt = 0; nt < 4; nt++) {
#pragma unroll
            for (int j = 0; j < 2; j++) {
                int d = n0 + wn * 32 + nt * 8 + 2 * (lane & 3) + j;
                float vd = v_s[d];
                float dj = dec_s[d];
#pragma unroll
                for (int mt = 0; mt < 2; mt++) {
#pragma unroll
                    for (int h = 0; h < 2; h++) {
                        float x = acc[mt][nt][h * 2 + j] + dj;
                        msum[mt * 2 + h] += vd * fast_tanh(x);
                    }
                }
            }
        }
    }

    // Cross-warp reduction
    float* red = (float*)(smem + RED_OFF);
    __syncthreads();
#pragma unroll
    for (int mt = 0; mt < 2; mt++)
#pragma unroll
        for (int h = 0; h < 2; h++) {
            int m = wm * 32 + mt * 16 + h * 8 + (lane >> 2);
            red[m * 16 + wn * 4 + (lane & 3)] = msum[mt * 2 + h];
        }
    __syncthreads();
    if (tid < 128) {
        float sum = 0.f;
#pragma unroll
        for (int x = 0; x < 16; x++) sum += red[tid * 16 + x];
        g_scores[row0 + tid] = sum;
    }
}

// ---------------------------------------------------------------------------
// ct kernel with FUSED softmax: each block redundantly computes its batch's
// softmax stats over T=2048 raw scores, builds its 128 weights in SMEM, then
// accumulates ct_d via atomics.
// ---------------------------------------------------------------------------
__global__ void ct_softmax_kernel(const float* __restrict__ prev_s,
                                  float* __restrict__ out) {
    const int b = blockIdx.y;
    const int chunk = blockIdx.x;   // 0..15
    const int tid = threadIdx.x;    // 256
    __shared__ float sred[256];
    __shared__ float w_s[128];

    const float* sc = g_scores + b * TT;

    // softmax stats over all 2048 scores (redundant per block; 8KB)
    float vals[8];
    float mx = -INFINITY;
#pragma unroll
    for (int i = 0; i < 8; i++) {
        vals[i] = sc[tid + i * 256];
        mx = fmaxf(mx, vals[i]);
    }
    sred[tid] = mx;
    __syncthreads();
    for (int s = 128; s > 0; s >>= 1) {
        if (tid < s) sred[tid] = fmaxf(sred[tid], sred[tid + s]);
        __syncthreads();
    }
    mx = sred[0];
    __syncthreads();
    float sum = 0.f;
#pragma unroll
    for (int i = 0; i < 8; i++) sum += __expf(vals[i] - mx);
    sred[tid] = sum;
    __syncthreads();
    for (int s = 128; s > 0; s >>= 1) {
        if (tid < s) sred[tid] += sred[tid + s];
        __syncthreads();
    }
    const float inv = 1.0f / sred[0];

    const int t0 = chunk * 128;
    if (tid < 128) w_s[tid] = __expf(sc[t0 + tid] - mx) * inv;
    __syncthreads();

    const float4* src =
        reinterpret_cast<const float4*>(prev_s + ((size_t)b * TT + t0) * HH);
    float4 acc = make_float4(0.f, 0.f, 0.f, 0.f);
#pragma unroll 4
    for (int t = 0; t < 128; t++) {
        float4 p = src[(size_t)t * 256 + tid];
        float at = w_s[t];
        acc.x += at * p.x;
        acc.y += at * p.y;
        acc.z += at * p.z;
        acc.w += at * p.w;
    }
    float* ctb = out + (size_t)b * HH + tid * 4;
    atomicAdd(ctb + 0, acc.x);
    atomicAdd(ctb + 1, acc.y);
    atomicAdd(ctb + 2, acc.z);
    atomicAdd(ctb + 3, acc.w);
}

// ---------------------------------------------------------------------------
extern "C" void kernel_launch(void* const* d_in, const int* in_sizes, int n_in,
                              void* d_out, int out_size) {
    const float* s_t    = (const float*)d_in[0];
    const float* prev_s = (const float*)d_in[1];
    const float* W_prev = (const float*)d_in[2];
    const float* W_s    = (const float*)d_in[3];
    const float* b_s    = (const float*)d_in[4];
    const float* v      = (const float*)d_in[5];
    float* out = (float*)d_out;

    static bool once = false;
    if (!once) {
        cudaFuncSetAttribute(score_kernel,
                             cudaFuncAttributeMaxDynamicSharedMemorySize, SMEM_BYTES);
        once = true;
    }

    __half *gA, *gB;
    cudaGetSymbolAddress((void**)&gA, g_A);
    cudaGetSymbolAddress((void**)&gB, g_B);

    init_kernel<<<64, 256>>>(s_t, out);
    conv_b_kernel<<<512, 256>>>(W_prev, gB);
    conv_split_copy_kernel<<<32768, 256>>>(prev_s, gA, out);
    dec_fea_kernel<<<HH / 128, 256>>>(s_t, W_s, b_s);
    score_kernel<<<(BB * TT) / 128, 512, SMEM_BYTES>>>(v);
    dim3 gt(16, BB);
    ct_softmax_kernel<<<gt, 256>>>(prev_s, out);
}

// round 11
// speedup vs baseline: 1.1319x; 1.1051x over previous
#include <cuda_runtime.h>
#include <cuda_fp16.h>
#include <math.h>
#include <cstdint>

#define BB 32
#define TT 2048
#define HH 1024

// Scratch (allocation-free rule: __device__ globals)
__device__ float g_decfea[BB * HH];
__device__ float g_scores[BB * TT];
__device__ __half g_B[(size_t)HH * HH];            // W_prev fp16 (2 MB), plain
// A split planes: per 32-k slab of each row: [32 hi | 32 lo] fp16 = 128B
__device__ __half g_A[(size_t)BB * TT * HH * 2];   // prev_s (268 MB)

// ---------------------------------------------------------------------------
// PTX helpers
// ---------------------------------------------------------------------------
__device__ __forceinline__ uint32_t smem_u32(const void* p) {
    uint32_t a;
    asm("{ .reg .u64 t; cvta.to.shared.u64 t, %1; cvt.u32.u64 %0, t; }" : "=r"(a) : "l"(p));
    return a;
}
__device__ __forceinline__ void cp_async16(uint32_t dst, const void* src) {
    asm volatile("cp.async.cg.shared.global [%0], [%1], 16;" :: "r"(dst), "l"(src) : "memory");
}
__device__ __forceinline__ void cp_commit() {
    asm volatile("cp.async.commit_group;" ::: "memory");
}
template <int N>
__device__ __forceinline__ void cp_wait() {
    asm volatile("cp.async.wait_group %0;" :: "n"(N) : "memory");
}
__device__ __forceinline__ void ldsm_x4(uint32_t addr, uint32_t& r0, uint32_t& r1,
                                        uint32_t& r2, uint32_t& r3) {
    asm volatile("ldmatrix.sync.aligned.m8n8.x4.shared.b16 {%0,%1,%2,%3}, [%4];"
                 : "=r"(r0), "=r"(r1), "=r"(r2), "=r"(r3) : "r"(addr));
}
__device__ __forceinline__ void mma_f32(float* c, const uint32_t* a, const uint32_t* b) {
    asm volatile(
        "mma.sync.aligned.m16n8k16.row.col.f32.f16.f16.f32 "
        "{%0,%1,%2,%3}, {%4,%5,%6,%7}, {%8,%9}, {%0,%1,%2,%3};"
        : "+f"(c[0]), "+f"(c[1]), "+f"(c[2]), "+f"(c[3])
        : "r"(a[0]), "r"(a[1]), "r"(a[2]), "r"(a[3]), "r"(b[0]), "r"(b[1]));
}
__device__ __forceinline__ float fast_tanh(float x) {
    float y;
    asm("tanh.approx.f32 %0, %1;" : "=f"(y) : "f"(x));
    return y;
}
__device__ __forceinline__ uint32_t pack_h2(__half a, __half b) {
    __half2 t = __halves2half2(a, b);
    return *reinterpret_cast<uint32_t*>(&t);
}
// fp16 split, UNSCALED residual: hi = f16(x), lo = f16(x - hi).
__device__ __forceinline__ void split2h(float x, float y, uint32_t& hi, uint32_t& lo) {
    __half hx = __float2half_rn(x), hy = __float2half_rn(y);
    __half lx = __float2half_rn(x - __half2float(hx));
    __half ly = __float2half_rn(y - __half2float(hy));
    hi = pack_h2(hx, hy);
    lo = pack_h2(lx, ly);
}

// ---------------------------------------------------------------------------
// A prepack + concat copy fused: reads prev_s once, writes split fp16 planes
// to g_A AND the raw fp32 row into out's prev_s_new region.
// ---------------------------------------------------------------------------
__global__ void conv_split_copy_kernel(const float* __restrict__ src,
                                       __half* __restrict__ dst,
                                       float* __restrict__ out) {
    size_t t = (size_t)blockIdx.x * 256 + threadIdx.x;
    int j = (int)(t & 3);
    size_t chunk = t >> 2;          // row*32 + slab
    int slab = (int)(chunk & 31);
    size_t row = chunk >> 5;        // 0..65535 = b*2048 + tt
    int b = (int)(row >> 11);
    int tt = (int)(row & 2047);

    const float* s = src + chunk * 32 + (size_t)j * 8;
    float4 f0 = *(const float4*)s;
    float4 f1 = *(const float4*)(s + 4);
    uint4 hi, lo;
    split2h(f0.x, f0.y, hi.x, lo.x);
    split2h(f0.z, f0.w, hi.y, lo.y);
    split2h(f1.x, f1.y, hi.z, lo.z);
    split2h(f1.z, f1.w, hi.w, lo.w);
    __half* d = dst + chunk * 64;
    *(uint4*)(d + j * 8) = hi;
    *(uint4*)(d + 32 + j * 8) = lo;

    // concat copy: prev_s_new[b, tt, :] = prev_s[b, tt, :]
    float* o = out + (size_t)BB * HH +
               ((size_t)b * (TT + 1) + tt) * HH + slab * 32 + j * 8;
    *(float4*)o = f0;
    *(float4*)(o + 4) = f1;
}

// B prepack: plain fp32 -> fp16 (row-major, k contiguous)
__global__ void conv_b_kernel(const float* __restrict__ src,
                              __half* __restrict__ dst) {
    size_t t = (size_t)blockIdx.x * 256 + threadIdx.x;  // x8 elems
    const float* s = src + t * 8;
    float4 f0 = *(const float4*)s;
    float4 f1 = *(const float4*)(s + 4);
    uint4 o;
    o.x = pack_h2(__float2half_rn(f0.x), __float2half_rn(f0.y));
    o.y = pack_h2(__float2half_rn(f0.z), __float2half_rn(f0.w));
    o.z = pack_h2(__float2half_rn(f1.x), __float2half_rn(f1.y));
    o.w = pack_h2(__float2half_rn(f1.z), __float2half_rn(f1.w));
    *(uint4*)(dst + t * 8) = o;
}

// ---------------------------------------------------------------------------
// Init kernel: zero ct_d region + write the s_t concat row.
// ---------------------------------------------------------------------------
__global__ void init_kernel(const float* __restrict__ s_t,
                            float* __restrict__ out) {
    int idx = blockIdx.x * 256 + threadIdx.x;   // 0..16383 (float4 units)
    if (idx < 8192) {
        reinterpret_cast<float4*>(out)[idx] = make_float4(0.f, 0.f, 0.f, 0.f);
    } else {
        int i = idx - 8192;                      // 0..8191 = b*256 + c
        int b = i >> 8, c = i & 255;
        float4 sv = reinterpret_cast<const float4*>(s_t + (size_t)b * HH)[c];
        float* pn = out + BB * HH + ((size_t)b * (TT + 1) + TT) * HH;
        reinterpret_cast<float4*>(pn)[c] = sv;
    }
}

// ---------------------------------------------------------------------------
// Kernel 1: dec_fea[b,d] = sum_h s_t[b,h] * W_s[d,h] + b_s[d]
// One thread per (b,d): grid 128 x block 256; lanes share a W_s row
// (broadcast), s_t (128 KB) served from L1/L2.
// ---------------------------------------------------------------------------
__global__ void dec_fea_kernel(const float* __restrict__ s_t,
                               const float* __restrict__ W_s,
                               const float* __restrict__ b_s) {
    const int tid = threadIdx.x;
    const int b = tid & 31;
    const int d = blockIdx.x * 8 + (tid >> 5);
    const float4* __restrict__ wrow =
        reinterpret_cast<const float4*>(W_s + (size_t)d * HH);
    const float4* __restrict__ srow =
        reinterpret_cast<const float4*>(s_t + (size_t)b * HH);
    float acc = 0.f;
#pragma unroll 8
    for (int k = 0; k < 256; k++) {
        float4 w = wrow[k];
        float4 s = srow[k];
        acc += w.x * s.x + w.y * s.y + w.z * s.z + w.w * s.w;
    }
    g_decfea[b * HH + d] = acc + __ldg(&b_s[d]);
}

// ---------------------------------------------------------------------------
// Kernel 2: fused score GEMM, fp16x2 split-A mma.sync (both passes f32-acc).
// CTA: 128 M x (8 n-chunks of 128), 4-stage cp.async ring, 1 barrier/slab.
// 16 warps = 4(m) x 4(n); warp tile 32m x 32n; SMEM rows padded to 80B.
// ---------------------------------------------------------------------------
constexpr int PLANE = 10240;        // 128 rows * 80B
constexpr int STAGE = 30720;        // A hi + A lo + B (one plane each)
constexpr int NSTAGE = 4;
constexpr int V_OFF = STAGE * NSTAGE;          // 122880
constexpr int DEC_OFF = V_OFF + 4096;
constexpr int RED_OFF = DEC_OFF + 4096;
constexpr int SMEM_BYTES = RED_OFF + 8192;     // 139264

__device__ __forceinline__ void fill_slab(uint32_t sb, int st, int s,
                                          int row0, int n0, int tid) {
#pragma unroll
    for (int it = 0; it < 3; it++) {
        int idx = tid + it * 512;           // 0..1535
        if (idx < 1024) {
            int m = idx >> 3;
            int p = (idx >> 2) & 1;
            int c = idx & 3;
            const __half* src =
                g_A + ((size_t)(row0 + m) * 32 + s) * 64 + p * 32 + c * 8;
            uint32_t dst = sb + (uint32_t)(st * STAGE) + p * PLANE + m * 80 + c * 16;
            cp_async16(dst, src);
        } else {
            int loc = idx - 1024;
            int m = loc >> 2;
            int c = loc & 3;
            const __half* src = g_B + (size_t)(n0 + m) * HH + s * 32 + c * 8;
            uint32_t dst = sb + (uint32_t)(st * STAGE) + 2 * PLANE + m * 80 + c * 16;
            cp_async16(dst, src);
        }
    }
}

__global__ void __launch_bounds__(512, 1)
score_kernel(const float* __restrict__ vvec) {
    extern __shared__ char smem[];
    const uint32_t sb = smem_u32(smem);
    const int tid = threadIdx.x;
    const int warp = tid >> 5;
    const int lane = tid & 31;
    const int wm = warp >> 2;   // 0..3
    const int wn = warp & 3;    // 0..3
    const int row0 = blockIdx.x * 128;
    const int b = blockIdx.x >> 4;

    float* v_s = (float*)(smem + V_OFF);
    float* dec_s = (float*)(smem + DEC_OFF);
    for (int i = tid; i < 1024; i += 512) {
        v_s[i] = vvec[i];
        dec_s[i] = g_decfea[b * 1024 + i];
    }
    __syncthreads();

    const int a_row = wm * 32 + (lane & 15);                    // + mt*16
    const int a_col = ((lane >> 4) << 4);                       // 0 or 16 bytes
    const int b_row = wn * 32 + (((lane >> 4) & 1) << 3) + (lane & 7);  // + q*16
    const int b_col = (((lane >> 3) & 1) << 4);

    float msum[4];
#pragma unroll
    for (int i = 0; i < 4; i++) msum[i] = 0.f;

#pragma unroll 1
    for (int nc = 0; nc < 8; nc++) {
        const int n0 = nc * 128;
        float acc[2][4][4];
#pragma unroll
        for (int mt = 0; mt < 2; mt++)
#pragma unroll
            for (int nt = 0; nt < 4; nt++)
#pragma unroll
                for (int c = 0; c < 4; c++) acc[mt][nt][c] = 0.f;

        fill_slab(sb, 0, 0, row0, n0, tid);
        cp_commit();
        fill_slab(sb, 1, 1, row0, n0, tid);
        cp_commit();
        fill_slab(sb, 2, 2, row0, n0, tid);
        cp_commit();

        int st = 0;
#pragma unroll 1
        for (int s = 0; s < 32; s++) {
            if (s <= 29) {
                cp_wait<2>();
            } else if (s == 30) {
                cp_wait<1>();
            } else {
                cp_wait<0>();
            }
            __syncthreads();  // single barrier per slab

            if (s < 29) {
                fill_slab(sb, (st + 3) & 3, s + 3, row0, n0, tid);
                cp_commit();
            }

            const uint32_t abase = sb + (uint32_t)(st * STAGE);
            const uint32_t bbase = abase + (uint32_t)(2 * PLANE);
#pragma unroll
            for (int ks = 0; ks < 2; ks++) {
                uint32_t ah[2][4], al[2][4];
#pragma unroll
                for (int mt = 0; mt < 2; mt++) {
                    uint32_t ra = abase + (a_row + mt * 16) * 80 + a_col + ks * 32;
                    ldsm_x4(ra, ah[mt][0], ah[mt][1], ah[mt][2], ah[mt][3]);
                    ldsm_x4(ra + PLANE, al[mt][0], al[mt][1], al[mt][2], al[mt][3]);
                }
#pragma unroll
                for (int q = 0; q < 2; q++) {
                    uint32_t bm[2][2];
                    {
                        uint32_t rb = bbase + (b_row + q * 16) * 80 + b_col + ks * 32;
                        uint32_t r0, r1, r2, r3;
                        ldsm_x4(rb, r0, r1, r2, r3);
                        bm[0][0] = r0; bm[0][1] = r1;
                        bm[1][0] = r2; bm[1][1] = r3;
                    }
#pragma unroll
                    for (int mt = 0; mt < 2; mt++)
#pragma unroll
                        for (int j = 0; j < 2; j++) {
                            mma_f32(acc[mt][2 * q + j], ah[mt], bm[j]);
                            mma_f32(acc[mt][2 * q + j], al[mt], bm[j]);
                        }
                }
            }
            st = (st + 1) & 3;
        }

        // Epilogue: msum += v[d]*tanh(acc + dec[d])
#pragma unroll
        for (int nt = 0; nt < 4; nt++) {
#pragma unroll
            for (int j = 0; j < 2; j++) {
                int d = n0 + wn * 32 + nt * 8 + 2 * (lane & 3) + j;
                float vd = v_s[d];
                float dj = dec_s[d];
#pragma unroll
                for (int mt = 0; mt < 2; mt++) {
#pragma unroll
                    for (int h = 0; h < 2; h++) {
                        float x = acc[mt][nt][h * 2 + j] + dj;
                        msum[mt * 2 + h] += vd * fast_tanh(x);
                    }
                }
            }
        }
    }

    // Cross-warp reduction
    float* red = (float*)(smem + RED_OFF);
    __syncthreads();
#pragma unroll
    for (int mt = 0; mt < 2; mt++)
#pragma unroll
        for (int h = 0; h < 2; h++) {
            int m = wm * 32 + mt * 16 + h * 8 + (lane >> 2);
            red[m * 16 + wn * 4 + (lane & 3)] = msum[mt * 2 + h];
        }
    __syncthreads();
    if (tid < 128) {
        float sum = 0.f;
#pragma unroll
        for (int x = 0; x < 16; x++) sum += red[tid * 16 + x];
        g_scores[row0 + tid] = sum;
    }
}

// ---------------------------------------------------------------------------
// ct kernel with FUSED softmax: each block redundantly computes its batch's
// softmax stats over T=2048 raw scores, builds its 128 weights in SMEM, then
// accumulates ct_d via atomics.
// ---------------------------------------------------------------------------
__global__ void ct_softmax_kernel(const float* __restrict__ prev_s,
                                  float* __restrict__ out) {
    const int b = blockIdx.y;
    const int chunk = blockIdx.x;   // 0..15
    const int tid = threadIdx.x;    // 256
    __shared__ float sred[256];
    __shared__ float w_s[128];

    const float* sc = g_scores + b * TT;

    float vals[8];
    float mx = -INFINITY;
#pragma unroll
    for (int i = 0; i < 8; i++) {
        vals[i] = sc[tid + i * 256];
        mx = fmaxf(mx, vals[i]);
    }
    sred[tid] = mx;
    __syncthreads();
    for (int s = 128; s > 0; s >>= 1) {
        if (tid < s) sred[tid] = fmaxf(sred[tid], sred[tid + s]);
        __syncthreads();
    }
    mx = sred[0];
    __syncthreads();
    float sum = 0.f;
#pragma unroll
    for (int i = 0; i < 8; i++) sum += __expf(vals[i] - mx);
    sred[tid] = sum;
    __syncthreads();
    for (int s = 128; s > 0; s >>= 1) {
        if (tid < s) sred[tid] += sred[tid + s];
        __syncthreads();
    }
    const float inv = 1.0f / sred[0];

    const int t0 = chunk * 128;
    if (tid < 128) w_s[tid] = __expf(sc[t0 + tid] - mx) * inv;
    __syncthreads();

    const float4* src =
        reinterpret_cast<const float4*>(prev_s + ((size_t)b * TT + t0) * HH);
    float4 acc = make_float4(0.f, 0.f, 0.f, 0.f);
#pragma unroll 4
    for (int t = 0; t < 128; t++) {
        float4 p = src[(size_t)t * 256 + tid];
        float at = w_s[t];
        acc.x += at * p.x;
        acc.y += at * p.y;
        acc.z += at * p.z;
        acc.w += at * p.w;
    }
    float* ctb = out + (size_t)b * HH + tid * 4;
    atomicAdd(ctb + 0, acc.x);
    atomicAdd(ctb + 1, acc.y);
    atomicAdd(ctb + 2, acc.z);
    atomicAdd(ctb + 3, acc.w);
}

// ---------------------------------------------------------------------------
extern "C" void kernel_launch(void* const* d_in, const int* in_sizes, int n_in,
                              void* d_out, int out_size) {
    const float* s_t    = (const float*)d_in[0];
    const float* prev_s = (const float*)d_in[1];
    const float* W_prev = (const float*)d_in[2];
    const float* W_s    = (const float*)d_in[3];
    const float* b_s    = (const float*)d_in[4];
    const float* v      = (const float*)d_in[5];
    float* out = (float*)d_out;

    static bool once = false;
    if (!once) {
        cudaFuncSetAttribute(score_kernel,
                             cudaFuncAttributeMaxDynamicSharedMemorySize, SMEM_BYTES);
        once = true;
    }

    __half *gA, *gB;
    cudaGetSymbolAddress((void**)&gA, g_A);
    cudaGetSymbolAddress((void**)&gB, g_B);

    init_kernel<<<64, 256>>>(s_t, out);
    conv_b_kernel<<<512, 256>>>(W_prev, gB);
    dec_fea_kernel<<<HH / 8, 256>>>(s_t, W_s, b_s);
    conv_split_copy_kernel<<<32768, 256>>>(prev_s, gA, out);
    score_kernel<<<(BB * TT) / 128, 512, SMEM_BYTES>>>(v);
    dim3 gt(16, BB);
    ct_softmax_kernel<<<gt, 256>>>(prev_s, out);
}

// round 12
// speedup vs baseline: 1.7188x; 1.5186x over previous
#include <cuda_runtime.h>
#include <cuda_fp16.h>
#include <math.h>
#include <cstdint>

#define BB 32
#define TT 2048
#define HH 1024

// Scratch (allocation-free rule: __device__ globals)
__device__ float g_decfea[BB * HH];
__device__ float g_scores[BB * TT];
__device__ __half g_B[(size_t)HH * HH];            // W_prev fp16 (2 MB)
__device__ __half g_A[(size_t)BB * TT * HH];       // prev_s fp16 (134 MB)

// ---------------------------------------------------------------------------
// PTX helpers
// ---------------------------------------------------------------------------
__device__ __forceinline__ uint32_t smem_u32(const void* p) {
    uint32_t a;
    asm("{ .reg .u64 t; cvta.to.shared.u64 t, %1; cvt.u32.u64 %0, t; }" : "=r"(a) : "l"(p));
    return a;
}
__device__ __forceinline__ void cp_async16(uint32_t dst, const void* src) {
    asm volatile("cp.async.cg.shared.global [%0], [%1], 16;" :: "r"(dst), "l"(src) : "memory");
}
__device__ __forceinline__ void cp_commit() {
    asm volatile("cp.async.commit_group;" ::: "memory");
}
template <int N>
__device__ __forceinline__ void cp_wait() {
    asm volatile("cp.async.wait_group %0;" :: "n"(N) : "memory");
}
__device__ __forceinline__ void ldsm_x4(uint32_t addr, uint32_t& r0, uint32_t& r1,
                                        uint32_t& r2, uint32_t& r3) {
    asm volatile("ldmatrix.sync.aligned.m8n8.x4.shared.b16 {%0,%1,%2,%3}, [%4];"
                 : "=r"(r0), "=r"(r1), "=r"(r2), "=r"(r3) : "r"(addr));
}
__device__ __forceinline__ void mma_f32(float* c, const uint32_t* a, const uint32_t* b) {
    asm volatile(
        "mma.sync.aligned.m16n8k16.row.col.f32.f16.f16.f32 "
        "{%0,%1,%2,%3}, {%4,%5,%6,%7}, {%8,%9}, {%0,%1,%2,%3};"
        : "+f"(c[0]), "+f"(c[1]), "+f"(c[2]), "+f"(c[3])
        : "r"(a[0]), "r"(a[1]), "r"(a[2]), "r"(a[3]), "r"(b[0]), "r"(b[1]));
}
__device__ __forceinline__ float fast_tanh(float x) {
    float y;
    asm("tanh.approx.f32 %0, %1;" : "=f"(y) : "f"(x));
    return y;
}
__device__ __forceinline__ uint32_t pack_h2(__half a, __half b) {
    __half2 t = __halves2half2(a, b);
    return *reinterpret_cast<uint32_t*>(&t);
}

// ---------------------------------------------------------------------------
// A prepack (plain fp16) + concat copy fused: reads prev_s once, writes fp16
// to g_A AND the raw fp32 row into out's prev_s_new region.
// ---------------------------------------------------------------------------
__global__ void conv_half_copy_kernel(const float* __restrict__ src,
                                      __half* __restrict__ dst,
                                      float* __restrict__ out) {
    size_t t = (size_t)blockIdx.x * 256 + threadIdx.x;  // x8 elems
    size_t e = t * 8;
    size_t row = e >> 10;               // b*2048 + tt
    int off = (int)(e & 1023);
    int b = (int)(row >> 11);
    int tt = (int)(row & 2047);

    float4 f0 = *(const float4*)(src + e);
    float4 f1 = *(const float4*)(src + e + 4);
    uint4 o;
    o.x = pack_h2(__float2half_rn(f0.x), __float2half_rn(f0.y));
    o.y = pack_h2(__float2half_rn(f0.z), __float2half_rn(f0.w));
    o.z = pack_h2(__float2half_rn(f1.x), __float2half_rn(f1.y));
    o.w = pack_h2(__float2half_rn(f1.z), __float2half_rn(f1.w));
    *(uint4*)(dst + e) = o;

    float* op = out + (size_t)BB * HH + ((size_t)b * (TT + 1) + tt) * HH + off;
    *(float4*)op = f0;
    *(float4*)(op + 4) = f1;
}

// B prepack: plain fp32 -> fp16 (row-major, k contiguous)
__global__ void conv_b_kernel(const float* __restrict__ src,
                              __half* __restrict__ dst) {
    size_t t = (size_t)blockIdx.x * 256 + threadIdx.x;  // x8 elems
    const float* s = src + t * 8;
    float4 f0 = *(const float4*)s;
    float4 f1 = *(const float4*)(s + 4);
    uint4 o;
    o.x = pack_h2(__float2half_rn(f0.x), __float2half_rn(f0.y));
    o.y = pack_h2(__float2half_rn(f0.z), __float2half_rn(f0.w));
    o.z = pack_h2(__float2half_rn(f1.x), __float2half_rn(f1.y));
    o.w = pack_h2(__float2half_rn(f1.z), __float2half_rn(f1.w));
    *(uint4*)(dst + t * 8) = o;
}

// ---------------------------------------------------------------------------
// Init kernel: zero ct_d region + write the s_t concat row.
// ---------------------------------------------------------------------------
__global__ void init_kernel(const float* __restrict__ s_t,
                            float* __restrict__ out) {
    int idx = blockIdx.x * 256 + threadIdx.x;   // 0..16383 (float4 units)
    if (idx < 8192) {
        reinterpret_cast<float4*>(out)[idx] = make_float4(0.f, 0.f, 0.f, 0.f);
    } else {
        int i = idx - 8192;                      // 0..8191 = b*256 + c
        int b = i >> 8, c = i & 255;
        float4 sv = reinterpret_cast<const float4*>(s_t + (size_t)b * HH)[c];
        float* pn = out + BB * HH + ((size_t)b * (TT + 1) + TT) * HH;
        reinterpret_cast<float4*>(pn)[c] = sv;
    }
}

// ---------------------------------------------------------------------------
// Kernel 1: dec_fea[b,d] = sum_h s_t[b,h] * W_s[d,h] + b_s[d]
// One thread per (b,d): grid 128 x block 256; lanes share a W_s row.
// ---------------------------------------------------------------------------
__global__ void dec_fea_kernel(const float* __restrict__ s_t,
                               const float* __restrict__ W_s,
                               const float* __restrict__ b_s) {
    const int tid = threadIdx.x;
    const int b = tid & 31;
    const int d = blockIdx.x * 8 + (tid >> 5);
    const float4* __restrict__ wrow =
        reinterpret_cast<const float4*>(W_s + (size_t)d * HH);
    const float4* __restrict__ srow =
        reinterpret_cast<const float4*>(s_t + (size_t)b * HH);
    float acc = 0.f;
#pragma unroll 8
    for (int k = 0; k < 256; k++) {
        float4 w = wrow[k];
        float4 s = srow[k];
        acc += w.x * s.x + w.y * s.y + w.z * s.z + w.w * s.w;
    }
    g_decfea[b * HH + d] = acc + __ldg(&b_s[d]);
}

// ---------------------------------------------------------------------------
// Kernel 2: fused score GEMM, plain-fp16 mma.sync (single pass, f32 acc).
// CTA: 128 M x (8 n-chunks of 128), 4-stage cp.async ring, 1 barrier/slab.
// 16 warps = 4(m) x 4(n); warp tile 32m x 32n; SMEM rows padded to 80B.
// ---------------------------------------------------------------------------
constexpr int PLANE = 10240;        // 128 rows * 80B
constexpr int STAGE = 20480;        // A plane + B plane
constexpr int NSTAGE = 4;
constexpr int V_OFF = STAGE * NSTAGE;          // 81920
constexpr int DEC_OFF = V_OFF + 4096;
constexpr int RED_OFF = DEC_OFF + 4096;
constexpr int SMEM_BYTES = RED_OFF + 8192;     // 98304

__device__ __forceinline__ void fill_slab(uint32_t sb, int st, int s,
                                          int row0, int n0, int tid) {
#pragma unroll
    for (int it = 0; it < 2; it++) {
        int idx = tid + it * 512;           // 0..1023
        bool isA = idx < 512;
        int loc = isA ? idx : idx - 512;
        int m = loc >> 2;
        int c = loc & 3;
        const __half* src = isA
            ? g_A + (size_t)(row0 + m) * HH + s * 32 + c * 8
            : g_B + (size_t)(n0 + m) * HH + s * 32 + c * 8;
        uint32_t dst = sb + (uint32_t)(st * STAGE) + (isA ? 0u : (uint32_t)PLANE) +
                       m * 80 + c * 16;
        cp_async16(dst, src);
    }
}

__global__ void __launch_bounds__(512, 1)
score_kernel(const float* __restrict__ vvec) {
    extern __shared__ char smem[];
    const uint32_t sb = smem_u32(smem);
    const int tid = threadIdx.x;
    const int warp = tid >> 5;
    const int lane = tid & 31;
    const int wm = warp >> 2;   // 0..3
    const int wn = warp & 3;    // 0..3
    const int row0 = blockIdx.x * 128;
    const int b = blockIdx.x >> 4;

    float* v_s = (float*)(smem + V_OFF);
    float* dec_s = (float*)(smem + DEC_OFF);
    for (int i = tid; i < 1024; i += 512) {
        v_s[i] = vvec[i];
        dec_s[i] = g_decfea[b * 1024 + i];
    }
    __syncthreads();

    const int a_row = wm * 32 + (lane & 15);                    // + mt*16
    const int a_col = ((lane >> 4) << 4);                       // 0 or 16 bytes
    const int b_row = wn * 32 + (((lane >> 4) & 1) << 3) + (lane & 7);  // + q*16
    const int b_col = (((lane >> 3) & 1) << 4);

    float msum[4];
#pragma unroll
    for (int i = 0; i < 4; i++) msum[i] = 0.f;

#pragma unroll 1
    for (int nc = 0; nc < 8; nc++) {
        const int n0 = nc * 128;
        float acc[2][4][4];
#pragma unroll
        for (int mt = 0; mt < 2; mt++)
#pragma unroll
            for (int nt = 0; nt < 4; nt++)
#pragma unroll
                for (int c = 0; c < 4; c++) acc[mt][nt][c] = 0.f;

        fill_slab(sb, 0, 0, row0, n0, tid);
        cp_commit();
        fill_slab(sb, 1, 1, row0, n0, tid);
        cp_commit();
        fill_slab(sb, 2, 2, row0, n0, tid);
        cp_commit();

        int st = 0;
#pragma unroll 1
        for (int s = 0; s < 32; s++) {
            if (s <= 29) {
                cp_wait<2>();
            } else if (s == 30) {
                cp_wait<1>();
            } else {
                cp_wait<0>();
            }
            __syncthreads();  // single barrier per slab

            if (s < 29) {
                fill_slab(sb, (st + 3) & 3, s + 3, row0, n0, tid);
                cp_commit();
            }

            const uint32_t abase = sb + (uint32_t)(st * STAGE);
            const uint32_t bbase = abase + (uint32_t)PLANE;
#pragma unroll
            for (int ks = 0; ks < 2; ks++) {
                uint32_t ah[2][4];
#pragma unroll
                for (int mt = 0; mt < 2; mt++) {
                    uint32_t ra = abase + (a_row + mt * 16) * 80 + a_col + ks * 32;
                    ldsm_x4(ra, ah[mt][0], ah[mt][1], ah[mt][2], ah[mt][3]);
                }
#pragma unroll
                for (int q = 0; q < 2; q++) {
                    uint32_t bm[2][2];
                    {
                        uint32_t rb = bbase + (b_row + q * 16) * 80 + b_col + ks * 32;
                        uint32_t r0, r1, r2, r3;
                        ldsm_x4(rb, r0, r1, r2, r3);
                        bm[0][0] = r0; bm[0][1] = r1;
                        bm[1][0] = r2; bm[1][1] = r3;
                    }
#pragma unroll
                    for (int mt = 0; mt < 2; mt++)
#pragma unroll
                        for (int j = 0; j < 2; j++)
                            mma_f32(acc[mt][2 * q + j], ah[mt], bm[j]);
                }
            }
            st = (st + 1) & 3;
        }

        // Epilogue: msum += v[d]*tanh(acc + dec[d])
#pragma unroll
        for (int nt = 0; nt < 4; nt++) {
#pragma unroll
            for (int j = 0; j < 2; j++) {
                int d = n0 + wn * 32 + nt * 8 + 2 * (lane & 3) + j;
                float vd = v_s[d];
                float dj = dec_s[d];
#pragma unroll
                for (int mt = 0; mt < 2; mt++) {
#pragma unroll
                    for (int h = 0; h < 2; h++) {
                        float x = acc[mt][nt][h * 2 + j] + dj;
                        msum[mt * 2 + h] += vd * fast_tanh(x);
                    }
                }
            }
        }
    }

    // Cross-warp reduction
    float* red = (float*)(smem + RED_OFF);
    __syncthreads();
#pragma unroll
    for (int mt = 0; mt < 2; mt++)
#pragma unroll
        for (int h = 0; h < 2; h++) {
            int m = wm * 32 + mt * 16 + h * 8 + (lane >> 2);
            red[m * 16 + wn * 4 + (lane & 3)] = msum[mt * 2 + h];
        }
    __syncthreads();
    if (tid < 128) {
        float sum = 0.f;
#pragma unroll
        for (int x = 0; x < 16; x++) sum += red[tid * 16 + x];
        g_scores[row0 + tid] = sum;
    }
}

// ---------------------------------------------------------------------------
// ct kernel with FUSED softmax: each block redundantly computes its batch's
// softmax stats over T=2048 raw scores, builds its 128 weights in SMEM, then
// accumulates ct_d via atomics.
// ---------------------------------------------------------------------------
__global__ void ct_softmax_kernel(const float* __restrict__ prev_s,
                                  float* __restrict__ out) {
    const int b = blockIdx.y;
    const int chunk = blockIdx.x;   // 0..15
    const int tid = threadIdx.x;    // 256
    __shared__ float sred[256];
    __shared__ float w_s[128];

    const float* sc = g_scores + b * TT;

    float vals[8];
    float mx = -INFINITY;
#pragma unroll
    for (int i = 0; i < 8; i++) {
        vals[i] = sc[tid + i * 256];
        mx = fmaxf(mx, vals[i]);
    }
    sred[tid] = mx;
    __syncthreads();
    for (int s = 128; s > 0; s >>= 1) {
        if (tid < s) sred[tid] = fmaxf(sred[tid], sred[tid + s]);
        __syncthreads();
    }
    mx = sred[0];
    __syncthreads();
    float sum = 0.f;
#pragma unroll
    for (int i = 0; i < 8; i++) sum += __expf(vals[i] - mx);
    sred[tid] = sum;
    __syncthreads();
    for (int s = 128; s > 0; s >>= 1) {
        if (tid < s) sred[tid] += sred[tid + s];
        __syncthreads();
    }
    const float inv = 1.0f / sred[0];

    const int t0 = chunk * 128;
    if (tid < 128) w_s[tid] = __expf(sc[t0 + tid] - mx) * inv;
    __syncthreads();

    const float4* src =
        reinterpret_cast<const float4*>(prev_s + ((size_t)b * TT + t0) * HH);
    float4 acc = make_float4(0.f, 0.f, 0.f, 0.f);
#pragma unroll 4
    for (int t = 0; t < 128; t++) {
        float4 p = src[(size_t)t * 256 + tid];
        float at = w_s[t];
        acc.x += at * p.x;
        acc.y += at * p.y;
        acc.z += at * p.z;
        acc.w += at * p.w;
    }
    float* ctb = out + (size_t)b * HH + tid * 4;
    atomicAdd(ctb + 0, acc.x);
    atomicAdd(ctb + 1, acc.y);
    atomicAdd(ctb + 2, acc.z);
    atomicAdd(ctb + 3, acc.w);
}

// ---------------------------------------------------------------------------
extern "C" void kernel_launch(void* const* d_in, const int* in_sizes, int n_in,
                              void* d_out, int out_size) {
    const float* s_t    = (const float*)d_in[0];
    const float* prev_s = (const float*)d_in[1];
    const float* W_prev = (const float*)d_in[2];
    const float* W_s    = (const float*)d_in[3];
    const float* b_s    = (const float*)d_in[4];
    const float* v      = (const float*)d_in[5];
    float* out = (float*)d_out;

    static bool once = false;
    if (!once) {
        cudaFuncSetAttribute(score_kernel,
                             cudaFuncAttributeMaxDynamicSharedMemorySize, SMEM_BYTES);
        once = true;
    }

    __half *gA, *gB;
    cudaGetSymbolAddress((void**)&gA, g_A);
    cudaGetSymbolAddress((void**)&gB, g_B);

    init_kernel<<<64, 256>>>(s_t, out);
    conv_b_kernel<<<512, 256>>>(W_prev, gB);
    dec_fea_kernel<<<HH / 8, 256>>>(s_t, W_s, b_s);
    conv_half_copy_kernel<<<32768, 256>>>(prev_s, gA, out);
    score_kernel<<<(BB * TT) / 128, 512, SMEM_BYTES>>>(v);
    dim3 gt(16, BB);
    ct_softmax_kernel<<<gt, 256>>>(prev_s, out);
}

// round 13
// speedup vs baseline: 2.0015x; 1.1644x over previous
#include <cuda_runtime.h>
#include <cuda_fp16.h>
#include <math.h>
#include <cstdint>

#define BB 32
#define TT 2048
#define HH 1024

// Scratch (allocation-free rule: __device__ globals)
__device__ float g_decfea[BB * HH];
__device__ float g_scores[BB * TT];
__device__ __half g_B[(size_t)HH * HH];            // W_prev fp16 (2 MB)
__device__ __half g_A[(size_t)BB * TT * HH];       // prev_s fp16 (134 MB)

// ---------------------------------------------------------------------------
// PTX helpers
// ---------------------------------------------------------------------------
__device__ __forceinline__ uint32_t smem_u32(const void* p) {
    uint32_t a;
    asm("{ .reg .u64 t; cvta.to.shared.u64 t, %1; cvt.u32.u64 %0, t; }" : "=r"(a) : "l"(p));
    return a;
}
__device__ __forceinline__ void cp_async16(uint32_t dst, const void* src) {
    asm volatile("cp.async.cg.shared.global [%0], [%1], 16;" :: "r"(dst), "l"(src) : "memory");
}
__device__ __forceinline__ void cp_commit() {
    asm volatile("cp.async.commit_group;" ::: "memory");
}
template <int N>
__device__ __forceinline__ void cp_wait() {
    asm volatile("cp.async.wait_group %0;" :: "n"(N) : "memory");
}
__device__ __forceinline__ void ldsm_x4(uint32_t addr, uint32_t& r0, uint32_t& r1,
                                        uint32_t& r2, uint32_t& r3) {
    asm volatile("ldmatrix.sync.aligned.m8n8.x4.shared.b16 {%0,%1,%2,%3}, [%4];"
                 : "=r"(r0), "=r"(r1), "=r"(r2), "=r"(r3) : "r"(addr));
}
__device__ __forceinline__ void mma_f32(float* c, const uint32_t* a, const uint32_t* b) {
    asm volatile(
        "mma.sync.aligned.m16n8k16.row.col.f32.f16.f16.f32 "
        "{%0,%1,%2,%3}, {%4,%5,%6,%7}, {%8,%9}, {%0,%1,%2,%3};"
        : "+f"(c[0]), "+f"(c[1]), "+f"(c[2]), "+f"(c[3])
        : "r"(a[0]), "r"(a[1]), "r"(a[2]), "r"(a[3]), "r"(b[0]), "r"(b[1]));
}
__device__ __forceinline__ float fast_tanh(float x) {
    float y;
    asm("tanh.approx.f32 %0, %1;" : "=f"(y) : "f"(x));
    return y;
}
__device__ __forceinline__ uint32_t pack_h2(__half a, __half b) {
    __half2 t = __halves2half2(a, b);
    return *reinterpret_cast<uint32_t*>(&t);
}

// ---------------------------------------------------------------------------
// A prepack (plain fp16) + concat copy fused.
// ---------------------------------------------------------------------------
__global__ void conv_half_copy_kernel(const float* __restrict__ src,
                                      __half* __restrict__ dst,
                                      float* __restrict__ out) {
    size_t t = (size_t)blockIdx.x * 256 + threadIdx.x;  // x8 elems
    size_t e = t * 8;
    size_t row = e >> 10;               // b*2048 + tt
    int off = (int)(e & 1023);
    int b = (int)(row >> 11);
    int tt = (int)(row & 2047);

    float4 f0 = *(const float4*)(src + e);
    float4 f1 = *(const float4*)(src + e + 4);
    uint4 o;
    o.x = pack_h2(__float2half_rn(f0.x), __float2half_rn(f0.y));
    o.y = pack_h2(__float2half_rn(f0.z), __float2half_rn(f0.w));
    o.z = pack_h2(__float2half_rn(f1.x), __float2half_rn(f1.y));
    o.w = pack_h2(__float2half_rn(f1.z), __float2half_rn(f1.w));
    *(uint4*)(dst + e) = o;

    float* op = out + (size_t)BB * HH + ((size_t)b * (TT + 1) + tt) * HH + off;
    *(float4*)op = f0;
    *(float4*)(op + 4) = f1;
}

// B prepack: plain fp32 -> fp16
__global__ void conv_b_kernel(const float* __restrict__ src,
                              __half* __restrict__ dst) {
    size_t t = (size_t)blockIdx.x * 256 + threadIdx.x;  // x8 elems
    const float* s = src + t * 8;
    float4 f0 = *(const float4*)s;
    float4 f1 = *(const float4*)(s + 4);
    uint4 o;
    o.x = pack_h2(__float2half_rn(f0.x), __float2half_rn(f0.y));
    o.y = pack_h2(__float2half_rn(f0.z), __float2half_rn(f0.w));
    o.z = pack_h2(__float2half_rn(f1.x), __float2half_rn(f1.y));
    o.w = pack_h2(__float2half_rn(f1.z), __float2half_rn(f1.w));
    *(uint4*)(dst + t * 8) = o;
}

// ---------------------------------------------------------------------------
// Init kernel: zero ct_d region + write the s_t concat row.
// ---------------------------------------------------------------------------
__global__ void init_kernel(const float* __restrict__ s_t,
                            float* __restrict__ out) {
    int idx = blockIdx.x * 256 + threadIdx.x;   // 0..16383 (float4 units)
    if (idx < 8192) {
        reinterpret_cast<float4*>(out)[idx] = make_float4(0.f, 0.f, 0.f, 0.f);
    } else {
        int i = idx - 8192;                      // 0..8191 = b*256 + c
        int b = i >> 8, c = i & 255;
        float4 sv = reinterpret_cast<const float4*>(s_t + (size_t)b * HH)[c];
        float* pn = out + BB * HH + ((size_t)b * (TT + 1) + TT) * HH;
        reinterpret_cast<float4*>(pn)[c] = sv;
    }
}

// ---------------------------------------------------------------------------
// Kernel 1: dec_fea[b,d] = sum_h s_t[b,h] * W_s[d,h] + b_s[d]
// ---------------------------------------------------------------------------
__global__ void dec_fea_kernel(const float* __restrict__ s_t,
                               const float* __restrict__ W_s,
                               const float* __restrict__ b_s) {
    const int tid = threadIdx.x;
    const int b = tid & 31;
    const int d = blockIdx.x * 8 + (tid >> 5);
    const float4* __restrict__ wrow =
        reinterpret_cast<const float4*>(W_s + (size_t)d * HH);
    const float4* __restrict__ srow =
        reinterpret_cast<const float4*>(s_t + (size_t)b * HH);
    float acc = 0.f;
#pragma unroll 8
    for (int k = 0; k < 256; k++) {
        float4 w = wrow[k];
        float4 s = srow[k];
        acc += w.x * s.x + w.y * s.y + w.z * s.z + w.w * s.w;
    }
    g_decfea[b * HH + d] = acc + __ldg(&b_s[d]);
}

// ---------------------------------------------------------------------------
// Kernel 2: fused score GEMM, plain-fp16 mma.sync, f32 acc.
// CTA: 64 M x (8 n-chunks of 128), 4-stage cp.async ring, 1 barrier/slab.
// 8 warps = 2(m) x 4(n); warp tile 32m x 32n; 2 CTAs/SM for finer tail.
// ---------------------------------------------------------------------------
constexpr int A_PLANE = 5120;       // 64 rows * 80B
constexpr int B_PLANE = 10240;      // 128 rows * 80B
constexpr int STAGE = A_PLANE + B_PLANE;       // 15360
constexpr int NSTAGE = 4;
constexpr int V_OFF = STAGE * NSTAGE;          // 61440
constexpr int DEC_OFF = V_OFF + 4096;
constexpr int RED_OFF = DEC_OFF + 4096;
constexpr int SMEM_BYTES = RED_OFF + 4096;     // 73728

__device__ __forceinline__ void fill_slab(uint32_t sb, int st, int s,
                                          int row0, int n0, int tid) {
#pragma unroll
    for (int it = 0; it < 3; it++) {
        int idx = tid + it * 256;           // 0..767
        if (idx < 256) {
            // A: 64 rows x 4 chunks of 16B
            int m = idx >> 2;
            int c = idx & 3;
            const __half* src = g_A + (size_t)(row0 + m) * HH + s * 32 + c * 8;
            uint32_t dst = sb + (uint32_t)(st * STAGE) + m * 80 + c * 16;
            cp_async16(dst, src);
        } else {
            // B: 128 rows x 4 chunks of 16B
            int loc = idx - 256;
            int m = loc >> 2;
            int c = loc & 3;
            const __half* src = g_B + (size_t)(n0 + m) * HH + s * 32 + c * 8;
            uint32_t dst = sb + (uint32_t)(st * STAGE) + A_PLANE + m * 80 + c * 16;
            cp_async16(dst, src);
        }
    }
}

__global__ void __launch_bounds__(256, 2)
score_kernel(const float* __restrict__ vvec) {
    extern __shared__ char smem[];
    const uint32_t sb = smem_u32(smem);
    const int tid = threadIdx.x;
    const int warp = tid >> 5;
    const int lane = tid & 31;
    const int wm = warp >> 2;   // 0..1
    const int wn = warp & 3;    // 0..3
    const int row0 = blockIdx.x * 64;
    const int b = blockIdx.x >> 5;    // 32 CTAs per batch (2048/64)

    float* v_s = (float*)(smem + V_OFF);
    float* dec_s = (float*)(smem + DEC_OFF);
    for (int i = tid; i < 1024; i += 256) {
        v_s[i] = vvec[i];
        dec_s[i] = g_decfea[b * 1024 + i];
    }
    __syncthreads();

    const int a_row = wm * 32 + (lane & 15);                    // + mt*16
    const int a_col = ((lane >> 4) << 4);                       // 0 or 16 bytes
    const int b_row = wn * 32 + (((lane >> 4) & 1) << 3) + (lane & 7);  // + q*16
    const int b_col = (((lane >> 3) & 1) << 4);

    float msum[4];
#pragma unroll
    for (int i = 0; i < 4; i++) msum[i] = 0.f;

#pragma unroll 1
    for (int nc = 0; nc < 8; nc++) {
        const int n0 = nc * 128;
        float acc[2][4][4];
#pragma unroll
        for (int mt = 0; mt < 2; mt++)
#pragma unroll
            for (int nt = 0; nt < 4; nt++)
#pragma unroll
                for (int c = 0; c < 4; c++) acc[mt][nt][c] = 0.f;

        fill_slab(sb, 0, 0, row0, n0, tid);
        cp_commit();
        fill_slab(sb, 1, 1, row0, n0, tid);
        cp_commit();
        fill_slab(sb, 2, 2, row0, n0, tid);
        cp_commit();

        int st = 0;
#pragma unroll 1
        for (int s = 0; s < 32; s++) {
            if (s <= 29) {
                cp_wait<2>();
            } else if (s == 30) {
                cp_wait<1>();
            } else {
                cp_wait<0>();
            }
            __syncthreads();  // single barrier per slab

            if (s < 29) {
                fill_slab(sb, (st + 3) & 3, s + 3, row0, n0, tid);
                cp_commit();
            }

            const uint32_t abase = sb + (uint32_t)(st * STAGE);
            const uint32_t bbase = abase + (uint32_t)A_PLANE;
#pragma unroll
            for (int ks = 0; ks < 2; ks++) {
                uint32_t ah[2][4];
#pragma unroll
                for (int mt = 0; mt < 2; mt++) {
                    uint32_t ra = abase + (a_row + mt * 16) * 80 + a_col + ks * 32;
                    ldsm_x4(ra, ah[mt][0], ah[mt][1], ah[mt][2], ah[mt][3]);
                }
#pragma unroll
                for (int q = 0; q < 2; q++) {
                    uint32_t bm[2][2];
                    {
                        uint32_t rb = bbase + (b_row + q * 16) * 80 + b_col + ks * 32;
                        uint32_t r0, r1, r2, r3;
                        ldsm_x4(rb, r0, r1, r2, r3);
                        bm[0][0] = r0; bm[0][1] = r1;
                        bm[1][0] = r2; bm[1][1] = r3;
                    }
#pragma unroll
                    for (int mt = 0; mt < 2; mt++)
#pragma unroll
                        for (int j = 0; j < 2; j++)
                            mma_f32(acc[mt][2 * q + j], ah[mt], bm[j]);
                }
            }
            st = (st + 1) & 3;
        }

        // Epilogue: msum += v[d]*tanh(acc + dec[d])
#pragma unroll
        for (int nt = 0; nt < 4; nt++) {
#pragma unroll
            for (int j = 0; j < 2; j++) {
                int d = n0 + wn * 32 + nt * 8 + 2 * (lane & 3) + j;
                float vd = v_s[d];
                float dj = dec_s[d];
#pragma unroll
                for (int mt = 0; mt < 2; mt++) {
#pragma unroll
                    for (int h = 0; h < 2; h++) {
                        float x = acc[mt][nt][h * 2 + j] + dj;
                        msum[mt * 2 + h] += vd * fast_tanh(x);
                    }
                }
            }
        }
    }

    // Cross-warp reduction (64 rows x 16 partials)
    float* red = (float*)(smem + RED_OFF);
    __syncthreads();
#pragma unroll
    for (int mt = 0; mt < 2; mt++)
#pragma unroll
        for (int h = 0; h < 2; h++) {
            int m = wm * 32 + mt * 16 + h * 8 + (lane >> 2);
            red[m * 16 + wn * 4 + (lane & 3)] = msum[mt * 2 + h];
        }
    __syncthreads();
    if (tid < 64) {
        float sum = 0.f;
#pragma unroll
        for (int x = 0; x < 16; x++) sum += red[tid * 16 + x];
        g_scores[row0 + tid] = sum;
    }
}

// ---------------------------------------------------------------------------
// ct kernel with FUSED softmax, reading fp16 g_A (halved traffic).
// ---------------------------------------------------------------------------
__global__ void ct_softmax_kernel(float* __restrict__ out) {
    const int b = blockIdx.y;
    const int chunk = blockIdx.x;   // 0..15
    const int tid = threadIdx.x;    // 256
    __shared__ float sred[256];
    __shared__ float w_s[128];

    const float* sc = g_scores + b * TT;

    float vals[8];
    float mx = -INFINITY;
#pragma unroll
    for (int i = 0; i < 8; i++) {
        vals[i] = sc[tid + i * 256];
        mx = fmaxf(mx, vals[i]);
    }
    sred[tid] = mx;
    __syncthreads();
    for (int s = 128; s > 0; s >>= 1) {
        if (tid < s) sred[tid] = fmaxf(sred[tid], sred[tid + s]);
        __syncthreads();
    }
    mx = sred[0];
    __syncthreads();
    float sum = 0.f;
#pragma unroll
    for (int i = 0; i < 8; i++) sum += __expf(vals[i] - mx);
    sred[tid] = sum;
    __syncthreads();
    for (int s = 128; s > 0; s >>= 1) {
        if (tid < s) sred[tid] += sred[tid + s];
        __syncthreads();
    }
    const float inv = 1.0f / sred[0];

    const int t0 = chunk * 128;
    if (tid < 128) w_s[tid] = __expf(sc[t0 + tid] - mx) * inv;
    __syncthreads();

    // fp16 source: 4 halves per thread per row (256 threads x 4 = 1024)
    const uint2* src =
        reinterpret_cast<const uint2*>(g_A + ((size_t)b * TT + t0) * HH);
    float acc[4] = {0.f, 0.f, 0.f, 0.f};
#pragma unroll 4
    for (int t = 0; t < 128; t++) {
        uint2 p = src[(size_t)t * 256 + tid];
        float at = w_s[t];
        float2 f0 = __half22float2(*reinterpret_cast<__half2*>(&p.x));
        float2 f1 = __half22float2(*reinterpret_cast<__half2*>(&p.y));
        acc[0] += at * f0.x;
        acc[1] += at * f0.y;
        acc[2] += at * f1.x;
        acc[3] += at * f1.y;
    }
    float* ctb = out + (size_t)b * HH + tid * 4;
    atomicAdd(ctb + 0, acc[0]);
    atomicAdd(ctb + 1, acc[1]);
    atomicAdd(ctb + 2, acc[2]);
    atomicAdd(ctb + 3, acc[3]);
}

// ---------------------------------------------------------------------------
extern "C" void kernel_launch(void* const* d_in, const int* in_sizes, int n_in,
                              void* d_out, int out_size) {
    const float* s_t    = (const float*)d_in[0];
    const float* prev_s = (const float*)d_in[1];
    const float* W_prev = (const float*)d_in[2];
    const float* W_s    = (const float*)d_in[3];
    const float* b_s    = (const float*)d_in[4];
    const float* v      = (const float*)d_in[5];
    float* out = (float*)d_out;

    static bool once = false;
    if (!once) {
        cudaFuncSetAttribute(score_kernel,
                             cudaFuncAttributeMaxDynamicSharedMemorySize, SMEM_BYTES);
        once = true;
    }

    __half *gA, *gB;
    cudaGetSymbolAddress((void**)&gA, g_A);
    cudaGetSymbolAddress((void**)&gB, g_B);

    init_kernel<<<64, 256>>>(s_t, out);
    conv_b_kernel<<<512, 256>>>(W_prev, gB);
    dec_fea_kernel<<<HH / 8, 256>>>(s_t, W_s, b_s);
    conv_half_copy_kernel<<<32768, 256>>>(prev_s, gA, out);
    score_kernel<<<(BB * TT) / 64, 256, SMEM_BYTES>>>(v);
    dim3 gt(16, BB);
    ct_softmax_kernel<<<gt, 256>>>(out);
}